// round 11
// baseline (speedup 1.0000x reference)
#include <cuda_runtime.h>
#include <cuda_bf16.h>

#define N_NODES 10000
#define NHID    128
#define NEDGE   320000
#define NT      79            // ceil(10000/128)
#define NPAD    (NT * 128)    // 10112
#define GEMM_SMEM 65536       // A+B tiles only

__device__ __forceinline__ unsigned smem_u32(const void* p) {
    unsigned a;
    asm("{ .reg .u64 t; cvta.to.shared.u64 t, %1; cvt.u32.u64 %0, t; }"
        : "=r"(a) : "l"(p));
    return a;
}

// ---------------- scratch ----------------
__device__ float          g_xw  [N_NODES * NHID];   // fp32 (self-loop term)
__device__ __nv_bfloat16  g_xwh [N_NODES * NHID];   // bf16 copy (neighbor gather)
__device__ __nv_bfloat16  g_hb  [NPAD   * NHID];    // pad rows stay 0 (zero-init, never written)
__device__ float          g_dinv[N_NODES];
__device__ int            g_cnt [N_NODES];          // zero-init; re-cleared by k_spmm each replay
__device__ int            g_base[N_NODES];
__device__ int            g_cur [N_NODES];          // zero-init; re-cleared by k_spmm each replay
__device__ int            g_src [NEDGE];

// ---- histogram of incoming edges at target ----
__global__ void k_hist(const int* __restrict__ p) {
    int e = blockIdx.x * blockDim.x + threadIdx.x;
    if (e < NEDGE) {
        int c = p[NEDGE + e];
        if ((unsigned)c >= N_NODES) c = 0;
        atomicAdd(&g_cnt[c], 1);
    }
}

// ---- exclusive prefix sum (single block, 1024 threads) ----
__global__ void __launch_bounds__(1024) k_scan() {
    __shared__ int sums[1024];
    const int CH = 10;                    // 1024*10 = 10240 >= N_NODES
    int t = threadIdx.x;
    int s = 0;
#pragma unroll
    for (int j = 0; j < CH; j++) {
        int n = t * CH + j;
        if (n < N_NODES) s += g_cnt[n];
    }
    sums[t] = s;
    __syncthreads();
    for (int off = 1; off < 1024; off <<= 1) {
        int v = (t >= off) ? sums[t - off] : 0;
        __syncthreads();
        sums[t] += v;
        __syncthreads();
    }
    int run = (t > 0) ? sums[t - 1] : 0;
#pragma unroll
    for (int j = 0; j < CH; j++) {
        int n = t * CH + j;
        if (n < N_NODES) { g_base[n] = run; run += g_cnt[n]; }
    }
}

// ---- CSR fill + dinv fused ----
__global__ void k_fill(const int* __restrict__ p) {
    int e = blockIdx.x * blockDim.x + threadIdx.x;
    if (e < N_NODES) g_dinv[e] = rsqrtf((float)g_cnt[e] + 1.0f);
    if (e < NEDGE) {
        int r = p[e], c = p[NEDGE + e];
        if ((unsigned)r >= N_NODES) r = 0;
        if ((unsigned)c >= N_NODES) c = 0;
        int pos = g_base[c] + atomicAdd(&g_cur[c], 1);
        g_src[pos] = r;
    }
}

// ---- xw = x @ W ; writes fp32 + bf16 copies ----
__global__ void k_xw(const float* __restrict__ x, const float* __restrict__ W) {
    __shared__ float xs[NHID];
    int n = blockIdx.x;
    int t = threadIdx.x;
    xs[t] = x[n * NHID + t];
    __syncthreads();
    float acc = 0.0f;
#pragma unroll 8
    for (int k = 0; k < NHID; k++)
        acc = fmaf(xs[k], W[k * NHID + t], acc);
    g_xw [n * NHID + t] = acc;
    g_xwh[n * NHID + t] = __float2bfloat16(acc);
}

// ---- SpMM gather (bf16 neighbor rows, fp32 accum) + self-loop + bias + relu ----
// Clears g_cnt/g_cur for the next graph replay.
// ORDER: every thread loads cnt FIRST, barrier, then thread 0 clears —
// otherwise warps disagree on cnt and diverge at in-loop barriers (round-10 bug).
__global__ void __launch_bounds__(128) k_spmm(const float* __restrict__ b) {
    __shared__ int   ssrc[64];
    __shared__ float swt [64];
    int c = blockIdx.x;
    int t = threadIdx.x;
    int base = g_base[c];
    int cnt  = g_cnt[c];
    __syncthreads();                                // all threads hold cnt
    if (t == 0) { g_cnt[c] = 0; g_cur[c] = 0; }     // safe replay cleanup
    float acc0 = 0.0f, acc1 = 0.0f;
    for (int chunk = 0; chunk < cnt; chunk += 64) {
        int m = min(64, cnt - chunk);
        __syncthreads();
        if (t < m) {
            int s = g_src[base + chunk + t];
            ssrc[t] = s;
            swt [t] = g_dinv[s];
        }
        __syncthreads();
        int i = 0;
        for (; i + 1 < m; i += 2) {
            acc0 = fmaf(swt[i],     __bfloat162float(g_xwh[ssrc[i]     * NHID + t]), acc0);
            acc1 = fmaf(swt[i + 1], __bfloat162float(g_xwh[ssrc[i + 1] * NHID + t]), acc1);
        }
        if (i < m)
            acc0 = fmaf(swt[i], __bfloat162float(g_xwh[ssrc[i] * NHID + t]), acc0);
    }
    float dc = g_dinv[c];
    float v  = dc * (acc0 + acc1) + dc * dc * g_xw[c * NHID + t] + b[t];
    g_hb[c * NHID + t] = __float2bfloat16(fmaxf(v, 0.0f));
}

// ---- out = h @ h^T : bf16 mma.sync + ldmatrix; register-direct epilogue ----
__global__ void __launch_bounds__(256) k_gemm(float* __restrict__ out) {
    extern __shared__ char smem[];
    int bi = blockIdx.y, bj = blockIdx.x;
    if (bj < bi) return;
    bool diag = (bi == bj);

    unsigned sA = smem_u32(smem);
    unsigned sB = sA + 32768u;

    int t = threadIdx.x, lane = t & 31, wid = t >> 5;
    const __nv_bfloat16* gA = g_hb + (size_t)bi * 128 * NHID;
    const __nv_bfloat16* gB = g_hb + (size_t)bj * 128 * NHID;

    // load tiles (8 passes x 256 threads x 16B); XOR-16B swizzle per row
#pragma unroll
    for (int p = 0; p < 8; p++) {
        int chunk = p * 256 + t;
        int row = chunk >> 4, kc = chunk & 15;
        unsigned off = (unsigned)row * 256u + (unsigned)((kc ^ (row & 7)) << 4);
        *(uint4*)(smem + off) = *(const uint4*)(gA + row * NHID + kc * 8);
        if (!diag)
            *(uint4*)(smem + 32768 + off) = *(const uint4*)(gB + row * NHID + kc * 8);
    }
    __syncthreads();

    unsigned bB = diag ? sA : sB;
    int wm = wid & 3;
    int wn = wid >> 2;
    int mat = lane >> 3, rin = lane & 7;
    int rowoff = rin + (mat & 1) * 8;
    int khalf  = mat >> 1;

    float acc[2][8][4] = {};

#pragma unroll
    for (int ks = 0; ks < 8; ks++) {
        int kc = ks * 2 + khalf;
        unsigned a[2][4];
#pragma unroll
        for (int mi = 0; mi < 2; mi++) {
            int row = wm * 32 + mi * 16 + rowoff;
            unsigned addr = sA + (unsigned)row * 256u + (unsigned)((kc ^ (row & 7)) << 4);
            asm volatile("ldmatrix.sync.aligned.m8n8.x4.shared.b16 {%0,%1,%2,%3}, [%4];"
                : "=r"(a[mi][0]), "=r"(a[mi][1]), "=r"(a[mi][2]), "=r"(a[mi][3])
                : "r"(addr));
        }
        unsigned bf[4][4];
#pragma unroll
        for (int nb = 0; nb < 4; nb++) {
            int row = wn * 64 + nb * 16 + rowoff;
            unsigned addr = bB + (unsigned)row * 256u + (unsigned)((kc ^ (row & 7)) << 4);
            asm volatile("ldmatrix.sync.aligned.m8n8.x4.shared.b16 {%0,%1,%2,%3}, [%4];"
                : "=r"(bf[nb][0]), "=r"(bf[nb][1]), "=r"(bf[nb][2]), "=r"(bf[nb][3])
                : "r"(addr));
        }
#pragma unroll
        for (int mi = 0; mi < 2; mi++)
#pragma unroll
            for (int nb = 0; nb < 4; nb++) {
                float* d0 = acc[mi][nb * 2 + 0];
                float* d1 = acc[mi][nb * 2 + 1];
                asm volatile(
                    "mma.sync.aligned.m16n8k16.row.col.f32.bf16.bf16.f32 "
                    "{%0,%1,%2,%3}, {%4,%5,%6,%7}, {%8,%9}, {%0,%1,%2,%3};"
                    : "+f"(d0[0]), "+f"(d0[1]), "+f"(d0[2]), "+f"(d0[3])
                    : "r"(a[mi][0]), "r"(a[mi][1]), "r"(a[mi][2]), "r"(a[mi][3]),
                      "r"(bf[nb][0]), "r"(bf[nb][2]));
                asm volatile(
                    "mma.sync.aligned.m16n8k16.row.col.f32.bf16.bf16.f32 "
                    "{%0,%1,%2,%3}, {%4,%5,%6,%7}, {%8,%9}, {%0,%1,%2,%3};"
                    : "+f"(d1[0]), "+f"(d1[1]), "+f"(d1[2]), "+f"(d1[3])
                    : "r"(a[mi][0]), "r"(a[mi][1]), "r"(a[mi][2]), "r"(a[mi][3]),
                      "r"(bf[nb][1]), "r"(bf[nb][3]));
            }
    }

    // register-direct epilogue (both paths 100% sector-efficient)
    int g = lane >> 2, tq = lane & 3;
    int r0 = bi * 128, c0 = bj * 128;
    bool interior = (bi < NT - 1) && (bj < NT - 1);

    if (interior) {
#pragma unroll
        for (int mi = 0; mi < 2; mi++)
#pragma unroll
            for (int ni = 0; ni < 8; ni++) {
                float* d = acc[mi][ni];
                int r = r0 + wm * 32 + mi * 16 + g;
                int c = c0 + wn * 64 + ni * 8 + 2 * tq;
                *(float2*)&out[(size_t)r * N_NODES + c]       = make_float2(d[0], d[1]);
                *(float2*)&out[(size_t)(r + 8) * N_NODES + c] = make_float2(d[2], d[3]);
                if (!diag) {
                    out[(size_t)c * N_NODES + r]           = d[0];
                    out[(size_t)(c + 1) * N_NODES + r]     = d[1];
                    out[(size_t)c * N_NODES + r + 8]       = d[2];
                    out[(size_t)(c + 1) * N_NODES + r + 8] = d[3];
                }
            }
    } else {
#pragma unroll
        for (int mi = 0; mi < 2; mi++)
#pragma unroll
            for (int ni = 0; ni < 8; ni++) {
                float* d = acc[mi][ni];
                int r = r0 + wm * 32 + mi * 16 + g;
                int c = c0 + wn * 64 + ni * 8 + 2 * tq;
#pragma unroll
                for (int q = 0; q < 4; q++) {
                    int rr = r + (q >> 1) * 8, cc = c + (q & 1);
                    if (rr < N_NODES && cc < N_NODES) {
                        out[(size_t)rr * N_NODES + cc] = d[q];
                        if (!diag) out[(size_t)cc * N_NODES + rr] = d[q];
                    }
                }
            }
    }
}

extern "C" void kernel_launch(void* const* d_in, const int* in_sizes, int n_in,
                              void* d_out, int out_size) {
    const float* x  = nullptr;
    const int*   ei = nullptr;
    const float* W  = nullptr;
    const float* b  = nullptr;
    for (int i = 0; i < n_in; i++) {
        switch (in_sizes[i]) {
            case N_NODES * NHID: x  = (const float*)d_in[i]; break;
            case 2 * NEDGE:      ei = (const int*)d_in[i];   break;
            case NHID * NHID:    W  = (const float*)d_in[i]; break;
            case NHID:           b  = (const float*)d_in[i]; break;
            default: break;
        }
    }
    float* out = (float*)d_out;

    static int smem_set = 0;
    if (!smem_set) {
        cudaFuncSetAttribute(k_gemm, cudaFuncAttributeMaxDynamicSharedMemorySize,
                             GEMM_SMEM);
        smem_set = 1;
    }

    k_hist <<<(NEDGE + 255) / 256, 256>>>(ei);
    k_scan <<<1, 1024>>>();
    k_fill <<<(NEDGE + 255) / 256, 256>>>(ei);
    k_xw   <<<N_NODES, NHID>>>(x, W);
    k_spmm <<<N_NODES, NHID>>>(b);
    dim3 gg(NT, NT);
    k_gemm <<<gg, 256, GEMM_SMEM>>>(out);
}

// round 12
// speedup vs baseline: 1.1079x; 1.1079x over previous
#include <cuda_runtime.h>
#include <cuda_bf16.h>

#define N_NODES 10000
#define NHID    128
#define NEDGE   320000
#define NT      79            // ceil(10000/128)
#define NPAD    (NT * 128)    // 10112
#define GEMM_SMEM 65536       // A+B tiles
#define XW_SMEM   81920       // W (64KB) + x tile (16KB)

__device__ __forceinline__ unsigned smem_u32(const void* p) {
    unsigned a;
    asm("{ .reg .u64 t; cvta.to.shared.u64 t, %1; cvt.u32.u64 %0, t; }"
        : "=r"(a) : "l"(p));
    return a;
}

// ---------------- scratch ----------------
__device__ float          g_xw  [N_NODES * NHID];
__device__ __nv_bfloat16  g_hb  [NPAD   * NHID];    // pad rows stay 0 (zero-init, never written)
__device__ float          g_dinv[N_NODES];
__device__ int            g_cnt [N_NODES];          // zero-init; re-cleared by k_spmm each replay
__device__ int            g_base[N_NODES];
__device__ int            g_cur [N_NODES];          // zero-init; re-cleared by k_spmm each replay
__device__ int            g_src [NEDGE];

// ---- histogram of incoming edges at target ----
__global__ void k_hist(const int* __restrict__ p) {
    int e = blockIdx.x * blockDim.x + threadIdx.x;
    if (e < NEDGE) {
        int c = p[NEDGE + e];
        if ((unsigned)c >= N_NODES) c = 0;
        atomicAdd(&g_cnt[c], 1);
    }
}

// ---- exclusive prefix sum (single block, 1024 threads) ----
__global__ void __launch_bounds__(1024) k_scan() {
    __shared__ int sums[1024];
    const int CH = 10;
    int t = threadIdx.x;
    int s = 0;
#pragma unroll
    for (int j = 0; j < CH; j++) {
        int n = t * CH + j;
        if (n < N_NODES) s += g_cnt[n];
    }
    sums[t] = s;
    __syncthreads();
    for (int off = 1; off < 1024; off <<= 1) {
        int v = (t >= off) ? sums[t - off] : 0;
        __syncthreads();
        sums[t] += v;
        __syncthreads();
    }
    int run = (t > 0) ? sums[t - 1] : 0;
#pragma unroll
    for (int j = 0; j < CH; j++) {
        int n = t * CH + j;
        if (n < N_NODES) { g_base[n] = run; run += g_cnt[n]; }
    }
}

// ---- CSR fill + dinv fused ----
__global__ void k_fill(const int* __restrict__ p) {
    int e = blockIdx.x * blockDim.x + threadIdx.x;
    if (e < N_NODES) g_dinv[e] = rsqrtf((float)g_cnt[e] + 1.0f);
    if (e < NEDGE) {
        int r = p[e], c = p[NEDGE + e];
        if ((unsigned)r >= N_NODES) r = 0;
        if ((unsigned)c >= N_NODES) c = 0;
        int pos = g_base[c] + atomicAdd(&g_cur[c], 1);
        g_src[pos] = r;
    }
}

// ---- xw = x @ W : tiled GEMM, W staged in smem once per 32-node block ----
__global__ void __launch_bounds__(256) k_xw(const float* __restrict__ x,
                                            const float* __restrict__ W) {
    extern __shared__ float sm[];
    float* Ws = sm;              // [128][128]
    float* xs = sm + NHID * NHID;  // [32][128]
    int t = threadIdx.x;
    int n0 = blockIdx.x * 32;

    // stage W (16384 floats, float4 x 16 passes)
#pragma unroll
    for (int i = 0; i < 16; i++) {
        int idx = (i * 256 + t) * 4;
        *(float4*)&Ws[idx] = *(const float4*)&W[idx];
    }
    // stage x tile (4096 floats, float4 x 4 passes), guard tail block
#pragma unroll
    for (int i = 0; i < 4; i++) {
        int idx = (i * 256 + t) * 4;
        int n = n0 + (idx >> 7);
        *(float4*)&xs[idx] = (n < N_NODES) ? *(const float4*)&x[(size_t)n * NHID + (idx & 127)]
                                           : make_float4(0.f, 0.f, 0.f, 0.f);
    }
    __syncthreads();

    int ty = t >> 5, tx = t & 31;      // 8 node-groups x 32 col-groups
    float acc[4][4] = {};
#pragma unroll 4
    for (int k = 0; k < NHID; k++) {
        float4 w4 = *(float4*)&Ws[k * NHID + tx * 4];   // conflict-free
        float xv0 = xs[(ty * 4 + 0) * NHID + k];         // warp-broadcast
        float xv1 = xs[(ty * 4 + 1) * NHID + k];
        float xv2 = xs[(ty * 4 + 2) * NHID + k];
        float xv3 = xs[(ty * 4 + 3) * NHID + k];
        acc[0][0] = fmaf(xv0, w4.x, acc[0][0]); acc[0][1] = fmaf(xv0, w4.y, acc[0][1]);
        acc[0][2] = fmaf(xv0, w4.z, acc[0][2]); acc[0][3] = fmaf(xv0, w4.w, acc[0][3]);
        acc[1][0] = fmaf(xv1, w4.x, acc[1][0]); acc[1][1] = fmaf(xv1, w4.y, acc[1][1]);
        acc[1][2] = fmaf(xv1, w4.z, acc[1][2]); acc[1][3] = fmaf(xv1, w4.w, acc[1][3]);
        acc[2][0] = fmaf(xv2, w4.x, acc[2][0]); acc[2][1] = fmaf(xv2, w4.y, acc[2][1]);
        acc[2][2] = fmaf(xv2, w4.z, acc[2][2]); acc[2][3] = fmaf(xv2, w4.w, acc[2][3]);
        acc[3][0] = fmaf(xv3, w4.x, acc[3][0]); acc[3][1] = fmaf(xv3, w4.y, acc[3][1]);
        acc[3][2] = fmaf(xv3, w4.z, acc[3][2]); acc[3][3] = fmaf(xv3, w4.w, acc[3][3]);
    }

#pragma unroll
    for (int i = 0; i < 4; i++) {
        int n = n0 + ty * 4 + i;
        if (n < N_NODES)
            *(float4*)&g_xw[(size_t)n * NHID + tx * 4] =
                make_float4(acc[i][0], acc[i][1], acc[i][2], acc[i][3]);
    }
}

// ---- SpMM gather (fp32) + self-loop + bias + relu + bf16 out ----
// Clears g_cnt/g_cur for the next graph replay (all threads read cnt first!).
__global__ void __launch_bounds__(128) k_spmm(const float* __restrict__ b) {
    __shared__ int   ssrc[64];
    __shared__ float swt [64];
    int c = blockIdx.x;
    int t = threadIdx.x;
    int base = g_base[c];
    int cnt  = g_cnt[c];
    __syncthreads();
    if (t == 0) { g_cnt[c] = 0; g_cur[c] = 0; }
    float acc0 = 0.0f, acc1 = 0.0f;
    for (int chunk = 0; chunk < cnt; chunk += 64) {
        int m = min(64, cnt - chunk);
        __syncthreads();
        if (t < m) {
            int s = g_src[base + chunk + t];
            ssrc[t] = s;
            swt [t] = g_dinv[s];
        }
        __syncthreads();
        int i = 0;
        for (; i + 1 < m; i += 2) {
            acc0 = fmaf(swt[i],     g_xw[ssrc[i]     * NHID + t], acc0);
            acc1 = fmaf(swt[i + 1], g_xw[ssrc[i + 1] * NHID + t], acc1);
        }
        if (i < m)
            acc0 = fmaf(swt[i], g_xw[ssrc[i] * NHID + t], acc0);
    }
    float dc = g_dinv[c];
    float v  = dc * (acc0 + acc1) + dc * dc * g_xw[c * NHID + t] + b[t];
    g_hb[c * NHID + t] = __float2bfloat16(fmaxf(v, 0.0f));
}

// ---- out = h @ h^T : bf16 mma.sync + ldmatrix; register-direct epilogue ----
__global__ void __launch_bounds__(256) k_gemm(float* __restrict__ out) {
    extern __shared__ char smem[];
    int bi = blockIdx.y, bj = blockIdx.x;
    if (bj < bi) return;
    bool diag = (bi == bj);

    unsigned sA = smem_u32(smem);
    unsigned sB = sA + 32768u;

    int t = threadIdx.x, lane = t & 31, wid = t >> 5;
    const __nv_bfloat16* gA = g_hb + (size_t)bi * 128 * NHID;
    const __nv_bfloat16* gB = g_hb + (size_t)bj * 128 * NHID;

#pragma unroll
    for (int p = 0; p < 8; p++) {
        int chunk = p * 256 + t;
        int row = chunk >> 4, kc = chunk & 15;
        unsigned off = (unsigned)row * 256u + (unsigned)((kc ^ (row & 7)) << 4);
        *(uint4*)(smem + off) = *(const uint4*)(gA + row * NHID + kc * 8);
        if (!diag)
            *(uint4*)(smem + 32768 + off) = *(const uint4*)(gB + row * NHID + kc * 8);
    }
    __syncthreads();

    unsigned bB = diag ? sA : sB;
    int wm = wid & 3;
    int wn = wid >> 2;
    int mat = lane >> 3, rin = lane & 7;
    int rowoff = rin + (mat & 1) * 8;
    int khalf  = mat >> 1;

    float acc[2][8][4] = {};

#pragma unroll
    for (int ks = 0; ks < 8; ks++) {
        int kc = ks * 2 + khalf;
        unsigned a[2][4];
#pragma unroll
        for (int mi = 0; mi < 2; mi++) {
            int row = wm * 32 + mi * 16 + rowoff;
            unsigned addr = sA + (unsigned)row * 256u + (unsigned)((kc ^ (row & 7)) << 4);
            asm volatile("ldmatrix.sync.aligned.m8n8.x4.shared.b16 {%0,%1,%2,%3}, [%4];"
                : "=r"(a[mi][0]), "=r"(a[mi][1]), "=r"(a[mi][2]), "=r"(a[mi][3])
                : "r"(addr));
        }
        unsigned bf[4][4];
#pragma unroll
        for (int nb = 0; nb < 4; nb++) {
            int row = wn * 64 + nb * 16 + rowoff;
            unsigned addr = bB + (unsigned)row * 256u + (unsigned)((kc ^ (row & 7)) << 4);
            asm volatile("ldmatrix.sync.aligned.m8n8.x4.shared.b16 {%0,%1,%2,%3}, [%4];"
                : "=r"(bf[nb][0]), "=r"(bf[nb][1]), "=r"(bf[nb][2]), "=r"(bf[nb][3])
                : "r"(addr));
        }
#pragma unroll
        for (int mi = 0; mi < 2; mi++)
#pragma unroll
            for (int nb = 0; nb < 4; nb++) {
                float* d0 = acc[mi][nb * 2 + 0];
                float* d1 = acc[mi][nb * 2 + 1];
                asm volatile(
                    "mma.sync.aligned.m16n8k16.row.col.f32.bf16.bf16.f32 "
                    "{%0,%1,%2,%3}, {%4,%5,%6,%7}, {%8,%9}, {%0,%1,%2,%3};"
                    : "+f"(d0[0]), "+f"(d0[1]), "+f"(d0[2]), "+f"(d0[3])
                    : "r"(a[mi][0]), "r"(a[mi][1]), "r"(a[mi][2]), "r"(a[mi][3]),
                      "r"(bf[nb][0]), "r"(bf[nb][2]));
                asm volatile(
                    "mma.sync.aligned.m16n8k16.row.col.f32.bf16.bf16.f32 "
                    "{%0,%1,%2,%3}, {%4,%5,%6,%7}, {%8,%9}, {%0,%1,%2,%3};"
                    : "+f"(d1[0]), "+f"(d1[1]), "+f"(d1[2]), "+f"(d1[3])
                    : "r"(a[mi][0]), "r"(a[mi][1]), "r"(a[mi][2]), "r"(a[mi][3]),
                      "r"(bf[nb][1]), "r"(bf[nb][3]));
            }
    }

    int g = lane >> 2, tq = lane & 3;
    int r0 = bi * 128, c0 = bj * 128;
    bool interior = (bi < NT - 1) && (bj < NT - 1);

    if (interior) {
#pragma unroll
        for (int mi = 0; mi < 2; mi++)
#pragma unroll
            for (int ni = 0; ni < 8; ni++) {
                float* d = acc[mi][ni];
                int r = r0 + wm * 32 + mi * 16 + g;
                int c = c0 + wn * 64 + ni * 8 + 2 * tq;
                *(float2*)&out[(size_t)r * N_NODES + c]       = make_float2(d[0], d[1]);
                *(float2*)&out[(size_t)(r + 8) * N_NODES + c] = make_float2(d[2], d[3]);
                if (!diag) {
                    out[(size_t)c * N_NODES + r]           = d[0];
                    out[(size_t)(c + 1) * N_NODES + r]     = d[1];
                    out[(size_t)c * N_NODES + r + 8]       = d[2];
                    out[(size_t)(c + 1) * N_NODES + r + 8] = d[3];
                }
            }
    } else {
#pragma unroll
        for (int mi = 0; mi < 2; mi++)
#pragma unroll
            for (int ni = 0; ni < 8; ni++) {
                float* d = acc[mi][ni];
                int r = r0 + wm * 32 + mi * 16 + g;
                int c = c0 + wn * 64 + ni * 8 + 2 * tq;
#pragma unroll
                for (int q = 0; q < 4; q++) {
                    int rr = r + (q >> 1) * 8, cc = c + (q & 1);
                    if (rr < N_NODES && cc < N_NODES) {
                        out[(size_t)rr * N_NODES + cc] = d[q];
                        if (!diag) out[(size_t)cc * N_NODES + rr] = d[q];
                    }
                }
            }
    }
}

extern "C" void kernel_launch(void* const* d_in, const int* in_sizes, int n_in,
                              void* d_out, int out_size) {
    const float* x  = nullptr;
    const int*   ei = nullptr;
    const float* W  = nullptr;
    const float* b  = nullptr;
    for (int i = 0; i < n_in; i++) {
        switch (in_sizes[i]) {
            case N_NODES * NHID: x  = (const float*)d_in[i]; break;
            case 2 * NEDGE:      ei = (const int*)d_in[i];   break;
            case NHID * NHID:    W  = (const float*)d_in[i]; break;
            case NHID:           b  = (const float*)d_in[i]; break;
            default: break;
        }
    }
    float* out = (float*)d_out;

    static int smem_set = 0;
    if (!smem_set) {
        cudaFuncSetAttribute(k_gemm, cudaFuncAttributeMaxDynamicSharedMemorySize,
                             GEMM_SMEM);
        cudaFuncSetAttribute(k_xw, cudaFuncAttributeMaxDynamicSharedMemorySize,
                             XW_SMEM);
        smem_set = 1;
    }

    k_hist <<<(NEDGE + 255) / 256, 256>>>(ei);
    k_scan <<<1, 1024>>>();
    k_fill <<<(NEDGE + 255) / 256, 256>>>(ei);
    k_xw   <<<(N_NODES + 31) / 32, 256, XW_SMEM>>>(x, W);
    k_spmm <<<N_NODES, NHID>>>(b);
    dim3 gg(NT, NT);
    k_gemm <<<gg, 256, GEMM_SMEM>>>(out);
}

// round 13
// speedup vs baseline: 1.1323x; 1.0220x over previous
#include <cuda_runtime.h>
#include <cuda_bf16.h>

#define N_NODES 10000
#define NHID    128
#define NEDGE   320000
#define NT      79            // ceil(10000/128)
#define NPAD    (NT * 128)    // 10112
#define GEMM_SMEM 65536       // A+B tiles
#define XW_SMEM   98304       // W (64KB) + x tile (32KB)

__device__ __forceinline__ unsigned smem_u32(const void* p) {
    unsigned a;
    asm("{ .reg .u64 t; cvta.to.shared.u64 t, %1; cvt.u32.u64 %0, t; }"
        : "=r"(a) : "l"(p));
    return a;
}

// ---------------- scratch ----------------
__device__ float          g_xw  [N_NODES * NHID];
__device__ __nv_bfloat16  g_hb  [NPAD   * NHID];    // pad rows stay 0 (zero-init, never written)
__device__ float          g_dinv[N_NODES];
__device__ int            g_cnt [N_NODES];          // zero-init; re-cleared by k_spmm each replay
__device__ int            g_base[N_NODES];
__device__ int            g_cur [N_NODES];          // zero-init; re-cleared by k_spmm each replay
__device__ int            g_src [NEDGE];

// ---- histogram of incoming edges at target ----
__global__ void k_hist(const int* __restrict__ p) {
    int e = blockIdx.x * blockDim.x + threadIdx.x;
    if (e < NEDGE) {
        int c = p[NEDGE + e];
        if ((unsigned)c >= N_NODES) c = 0;
        atomicAdd(&g_cnt[c], 1);
    }
}

// ---- exclusive prefix sum + dinv (single block, 1024 threads) ----
__global__ void __launch_bounds__(1024) k_scan() {
    __shared__ int sums[1024];
    const int CH = 10;
    int t = threadIdx.x;
    int s = 0;
#pragma unroll
    for (int j = 0; j < CH; j++) {
        int n = t * CH + j;
        if (n < N_NODES) s += g_cnt[n];
    }
    sums[t] = s;
    __syncthreads();
    for (int off = 1; off < 1024; off <<= 1) {
        int v = (t >= off) ? sums[t - off] : 0;
        __syncthreads();
        sums[t] += v;
        __syncthreads();
    }
    int run = (t > 0) ? sums[t - 1] : 0;
#pragma unroll
    for (int j = 0; j < CH; j++) {
        int n = t * CH + j;
        if (n < N_NODES) {
            int cn = g_cnt[n];
            g_base[n] = run;
            g_dinv[n] = rsqrtf((float)cn + 1.0f);
            run += cn;
        }
    }
}

// ---- CSR fill ----
__global__ void k_fill(const int* __restrict__ p) {
    int e = blockIdx.x * blockDim.x + threadIdx.x;
    if (e < NEDGE) {
        int r = p[e], c = p[NEDGE + e];
        if ((unsigned)r >= N_NODES) r = 0;
        if ((unsigned)c >= N_NODES) c = 0;
        int pos = g_base[c] + atomicAdd(&g_cur[c], 1);
        g_src[pos] = r;
    }
}

// ---- xw = x @ W : tiled GEMM, 64 nodes/block, 512 threads, ~1 wave ----
__global__ void __launch_bounds__(512) k_xw(const float* __restrict__ x,
                                            const float* __restrict__ W) {
    extern __shared__ float sm[];
    float* Ws = sm;                 // [128][128]
    float* xs = sm + NHID * NHID;   // [64][128]
    int t = threadIdx.x;
    int n0 = blockIdx.x * 64;

    // stage W (16384 floats, float4 x 8 passes of 512 threads)
#pragma unroll
    for (int i = 0; i < 8; i++) {
        int idx = (i * 512 + t) * 4;
        *(float4*)&Ws[idx] = *(const float4*)&W[idx];
    }
    // stage x tile (8192 floats, float4 x 4 passes), guard tail block
#pragma unroll
    for (int i = 0; i < 4; i++) {
        int idx = (i * 512 + t) * 4;
        int n = n0 + (idx >> 7);
        *(float4*)&xs[idx] = (n < N_NODES) ? *(const float4*)&x[(size_t)n * NHID + (idx & 127)]
                                           : make_float4(0.f, 0.f, 0.f, 0.f);
    }
    __syncthreads();

    int ty = t >> 5, tx = t & 31;      // 16 node-groups x 32 col-groups
    float acc[4][4] = {};
#pragma unroll 4
    for (int k = 0; k < NHID; k++) {
        float4 w4 = *(float4*)&Ws[k * NHID + tx * 4];   // conflict-free
        float xv0 = xs[(ty * 4 + 0) * NHID + k];         // warp-broadcast
        float xv1 = xs[(ty * 4 + 1) * NHID + k];
        float xv2 = xs[(ty * 4 + 2) * NHID + k];
        float xv3 = xs[(ty * 4 + 3) * NHID + k];
        acc[0][0] = fmaf(xv0, w4.x, acc[0][0]); acc[0][1] = fmaf(xv0, w4.y, acc[0][1]);
        acc[0][2] = fmaf(xv0, w4.z, acc[0][2]); acc[0][3] = fmaf(xv0, w4.w, acc[0][3]);
        acc[1][0] = fmaf(xv1, w4.x, acc[1][0]); acc[1][1] = fmaf(xv1, w4.y, acc[1][1]);
        acc[1][2] = fmaf(xv1, w4.z, acc[1][2]); acc[1][3] = fmaf(xv1, w4.w, acc[1][3]);
        acc[2][0] = fmaf(xv2, w4.x, acc[2][0]); acc[2][1] = fmaf(xv2, w4.y, acc[2][1]);
        acc[2][2] = fmaf(xv2, w4.z, acc[2][2]); acc[2][3] = fmaf(xv2, w4.w, acc[2][3]);
        acc[3][0] = fmaf(xv3, w4.x, acc[3][0]); acc[3][1] = fmaf(xv3, w4.y, acc[3][1]);
        acc[3][2] = fmaf(xv3, w4.z, acc[3][2]); acc[3][3] = fmaf(xv3, w4.w, acc[3][3]);
    }

#pragma unroll
    for (int i = 0; i < 4; i++) {
        int n = n0 + ty * 4 + i;
        if (n < N_NODES)
            *(float4*)&g_xw[(size_t)n * NHID + tx * 4] =
                make_float4(acc[i][0], acc[i][1], acc[i][2], acc[i][3]);
    }
}

// ---- SpMM gather (fp32) + self-loop + bias + relu + bf16 out ----
__global__ void __launch_bounds__(128) k_spmm(const float* __restrict__ b) {
    __shared__ int   ssrc[64];
    __shared__ float swt [64];
    int c = blockIdx.x;
    int t = threadIdx.x;
    int base = g_base[c];
    int cnt  = g_cnt[c];
    __syncthreads();                                // all threads hold cnt
    if (t == 0) { g_cnt[c] = 0; g_cur[c] = 0; }     // safe replay cleanup
    float acc0 = 0.0f, acc1 = 0.0f;
    for (int chunk = 0; chunk < cnt; chunk += 64) {
        int m = min(64, cnt - chunk);
        __syncthreads();
        if (t < m) {
            int s = g_src[base + chunk + t];
            ssrc[t] = s;
            swt [t] = g_dinv[s];
        }
        __syncthreads();
        int i = 0;
        for (; i + 1 < m; i += 2) {
            acc0 = fmaf(swt[i],     g_xw[ssrc[i]     * NHID + t], acc0);
            acc1 = fmaf(swt[i + 1], g_xw[ssrc[i + 1] * NHID + t], acc1);
        }
        if (i < m)
            acc0 = fmaf(swt[i], g_xw[ssrc[i] * NHID + t], acc0);
    }
    float dc = g_dinv[c];
    float v  = dc * (acc0 + acc1) + dc * dc * g_xw[c * NHID + t] + b[t];
    g_hb[c * NHID + t] = __float2bfloat16(fmaxf(v, 0.0f));
}

// ---- out = h @ h^T : bf16 mma.sync + ldmatrix; register-direct epilogue ----
__global__ void __launch_bounds__(256) k_gemm(float* __restrict__ out) {
    extern __shared__ char smem[];
    int bi = blockIdx.y, bj = blockIdx.x;
    if (bj < bi) return;
    bool diag = (bi == bj);

    unsigned sA = smem_u32(smem);
    unsigned sB = sA + 32768u;

    int t = threadIdx.x, lane = t & 31, wid = t >> 5;
    const __nv_bfloat16* gA = g_hb + (size_t)bi * 128 * NHID;
    const __nv_bfloat16* gB = g_hb + (size_t)bj * 128 * NHID;

#pragma unroll
    for (int p = 0; p < 8; p++) {
        int chunk = p * 256 + t;
        int row = chunk >> 4, kc = chunk & 15;
        unsigned off = (unsigned)row * 256u + (unsigned)((kc ^ (row & 7)) << 4);
        *(uint4*)(smem + off) = *(const uint4*)(gA + row * NHID + kc * 8);
        if (!diag)
            *(uint4*)(smem + 32768 + off) = *(const uint4*)(gB + row * NHID + kc * 8);
    }
    __syncthreads();

    unsigned bB = diag ? sA : sB;
    int wm = wid & 3;
    int wn = wid >> 2;
    int mat = lane >> 3, rin = lane & 7;
    int rowoff = rin + (mat & 1) * 8;
    int khalf  = mat >> 1;

    float acc[2][8][4] = {};

#pragma unroll
    for (int ks = 0; ks < 8; ks++) {
        int kc = ks * 2 + khalf;
        unsigned a[2][4];
#pragma unroll
        for (int mi = 0; mi < 2; mi++) {
            int row = wm * 32 + mi * 16 + rowoff;
            unsigned addr = sA + (unsigned)row * 256u + (unsigned)((kc ^ (row & 7)) << 4);
            asm volatile("ldmatrix.sync.aligned.m8n8.x4.shared.b16 {%0,%1,%2,%3}, [%4];"
                : "=r"(a[mi][0]), "=r"(a[mi][1]), "=r"(a[mi][2]), "=r"(a[mi][3])
                : "r"(addr));
        }
        unsigned bf[4][4];
#pragma unroll
        for (int nb = 0; nb < 4; nb++) {
            int row = wn * 64 + nb * 16 + rowoff;
            unsigned addr = bB + (unsigned)row * 256u + (unsigned)((kc ^ (row & 7)) << 4);
            asm volatile("ldmatrix.sync.aligned.m8n8.x4.shared.b16 {%0,%1,%2,%3}, [%4];"
                : "=r"(bf[nb][0]), "=r"(bf[nb][1]), "=r"(bf[nb][2]), "=r"(bf[nb][3])
                : "r"(addr));
        }
#pragma unroll
        for (int mi = 0; mi < 2; mi++)
#pragma unroll
            for (int nb = 0; nb < 4; nb++) {
                float* d0 = acc[mi][nb * 2 + 0];
                float* d1 = acc[mi][nb * 2 + 1];
                asm volatile(
                    "mma.sync.aligned.m16n8k16.row.col.f32.bf16.bf16.f32 "
                    "{%0,%1,%2,%3}, {%4,%5,%6,%7}, {%8,%9}, {%0,%1,%2,%3};"
                    : "+f"(d0[0]), "+f"(d0[1]), "+f"(d0[2]), "+f"(d0[3])
                    : "r"(a[mi][0]), "r"(a[mi][1]), "r"(a[mi][2]), "r"(a[mi][3]),
                      "r"(bf[nb][0]), "r"(bf[nb][2]));
                asm volatile(
                    "mma.sync.aligned.m16n8k16.row.col.f32.bf16.bf16.f32 "
                    "{%0,%1,%2,%3}, {%4,%5,%6,%7}, {%8,%9}, {%0,%1,%2,%3};"
                    : "+f"(d1[0]), "+f"(d1[1]), "+f"(d1[2]), "+f"(d1[3])
                    : "r"(a[mi][0]), "r"(a[mi][1]), "r"(a[mi][2]), "r"(a[mi][3]),
                      "r"(bf[nb][1]), "r"(bf[nb][3]));
            }
    }

    int g = lane >> 2, tq = lane & 3;
    int r0 = bi * 128, c0 = bj * 128;
    bool interior = (bi < NT - 1) && (bj < NT - 1);

    if (interior) {
#pragma unroll
        for (int mi = 0; mi < 2; mi++)
#pragma unroll
            for (int ni = 0; ni < 8; ni++) {
                float* d = acc[mi][ni];
                int r = r0 + wm * 32 + mi * 16 + g;
                int c = c0 + wn * 64 + ni * 8 + 2 * tq;
                *(float2*)&out[(size_t)r * N_NODES + c]       = make_float2(d[0], d[1]);
                *(float2*)&out[(size_t)(r + 8) * N_NODES + c] = make_float2(d[2], d[3]);
                if (!diag) {
                    out[(size_t)c * N_NODES + r]           = d[0];
                    out[(size_t)(c + 1) * N_NODES + r]     = d[1];
                    out[(size_t)c * N_NODES + r + 8]       = d[2];
                    out[(size_t)(c + 1) * N_NODES + r + 8] = d[3];
                }
            }
    } else {
#pragma unroll
        for (int mi = 0; mi < 2; mi++)
#pragma unroll
            for (int ni = 0; ni < 8; ni++) {
                float* d = acc[mi][ni];
                int r = r0 + wm * 32 + mi * 16 + g;
                int c = c0 + wn * 64 + ni * 8 + 2 * tq;
#pragma unroll
                for (int q = 0; q < 4; q++) {
                    int rr = r + (q >> 1) * 8, cc = c + (q & 1);
                    if (rr < N_NODES && cc < N_NODES) {
                        out[(size_t)rr * N_NODES + cc] = d[q];
                        if (!diag) out[(size_t)cc * N_NODES + rr] = d[q];
                    }
                }
            }
    }
}

extern "C" void kernel_launch(void* const* d_in, const int* in_sizes, int n_in,
                              void* d_out, int out_size) {
    const float* x  = nullptr;
    const int*   ei = nullptr;
    const float* W  = nullptr;
    const float* b  = nullptr;
    for (int i = 0; i < n_in; i++) {
        switch (in_sizes[i]) {
            case N_NODES * NHID: x  = (const float*)d_in[i]; break;
            case 2 * NEDGE:      ei = (const int*)d_in[i];   break;
            case NHID * NHID:    W  = (const float*)d_in[i]; break;
            case NHID:           b  = (const float*)d_in[i]; break;
            default: break;
        }
    }
    float* out = (float*)d_out;

    static cudaStream_t s2 = nullptr;
    static cudaEvent_t  evFork = nullptr, evJoin = nullptr;
    static int initialized = 0;
    if (!initialized) {
        cudaFuncSetAttribute(k_gemm, cudaFuncAttributeMaxDynamicSharedMemorySize,
                             GEMM_SMEM);
        cudaFuncSetAttribute(k_xw, cudaFuncAttributeMaxDynamicSharedMemorySize,
                             XW_SMEM);
        cudaStreamCreateWithFlags(&s2, cudaStreamNonBlocking);
        cudaEventCreateWithFlags(&evFork, cudaEventDisableTiming);
        cudaEventCreateWithFlags(&evJoin, cudaEventDisableTiming);
        initialized = 1;
    }

    // fork: k_xw runs concurrent with the CSR-build chain
    cudaEventRecord(evFork, 0);
    cudaStreamWaitEvent(s2, evFork, 0);
    k_xw<<<(N_NODES + 63) / 64, 512, XW_SMEM, s2>>>(x, W);
    cudaEventRecord(evJoin, s2);

    k_hist <<<(NEDGE + 255) / 256, 256>>>(ei);
    k_scan <<<1, 1024>>>();
    k_fill <<<(NEDGE + 255) / 256, 256>>>(ei);

    // join: k_spmm needs both g_xw and the CSR
    cudaStreamWaitEvent(0, evJoin, 0);
    k_spmm <<<N_NODES, NHID>>>(b);
    dim3 gg(NT, NT);
    k_gemm <<<gg, 256, GEMM_SMEM>>>(out);
}

// round 14
// speedup vs baseline: 1.2137x; 1.0719x over previous
#include <cuda_runtime.h>
#include <cuda_bf16.h>

#define N_NODES 10000
#define NHID    128
#define NEDGE   320000
#define NT      79            // ceil(10000/128)
#define NPAD    (NT * 128)    // 10112
#define BUCKET  128           // slots per node; 17-sigma headroom over mean degree 32
#define GEMM_SMEM 65536       // A+B tiles
#define XW_SMEM   98304       // W (64KB) + x tile (32KB)

__device__ __forceinline__ unsigned smem_u32(const void* p) {
    unsigned a;
    asm("{ .reg .u64 t; cvta.to.shared.u64 t, %1; cvt.u32.u64 %0, t; }"
        : "=r"(a) : "l"(p));
    return a;
}

// ---------------- scratch ----------------
__device__ float          g_xw  [N_NODES * NHID];
__device__ __nv_bfloat16  g_hb  [NPAD   * NHID];    // pad rows stay 0 (zero-init, never written)
__device__ float          g_dinv[N_NODES];
__device__ int            g_cnt [N_NODES];          // zero-init; re-cleared by k_spmm each replay
__device__ int            g_src [N_NODES * BUCKET]; // bucketed adjacency (src nodes per target)

// ---- bucketed CSR build: histogram + fill in ONE pass ----
__global__ void k_fill2(const int* __restrict__ p) {
    int e = blockIdx.x * blockDim.x + threadIdx.x;
    if (e < NEDGE) {
        int r = p[e], c = p[NEDGE + e];
        if ((unsigned)r >= N_NODES) r = 0;
        if ((unsigned)c >= N_NODES) c = 0;
        int pos = atomicAdd(&g_cnt[c], 1);
        if (pos < BUCKET) g_src[c * BUCKET + pos] = r;   // statistically never clamps
    }
}

// ---- dinv = rsqrt(deg + 1) ----
__global__ void k_dinv() {
    int i = blockIdx.x * blockDim.x + threadIdx.x;
    if (i < N_NODES) g_dinv[i] = rsqrtf((float)g_cnt[i] + 1.0f);
}

// ---- xw = x @ W : tiled GEMM, 64 nodes/block, 512 threads (forked stream) ----
__global__ void __launch_bounds__(512) k_xw(const float* __restrict__ x,
                                            const float* __restrict__ W) {
    extern __shared__ float sm[];
    float* Ws = sm;                 // [128][128]
    float* xs = sm + NHID * NHID;   // [64][128]
    int t = threadIdx.x;
    int n0 = blockIdx.x * 64;

#pragma unroll
    for (int i = 0; i < 8; i++) {
        int idx = (i * 512 + t) * 4;
        *(float4*)&Ws[idx] = *(const float4*)&W[idx];
    }
#pragma unroll
    for (int i = 0; i < 4; i++) {
        int idx = (i * 512 + t) * 4;
        int n = n0 + (idx >> 7);
        *(float4*)&xs[idx] = (n < N_NODES) ? *(const float4*)&x[(size_t)n * NHID + (idx & 127)]
                                           : make_float4(0.f, 0.f, 0.f, 0.f);
    }
    __syncthreads();

    int ty = t >> 5, tx = t & 31;
    float acc[4][4] = {};
#pragma unroll 4
    for (int k = 0; k < NHID; k++) {
        float4 w4 = *(float4*)&Ws[k * NHID + tx * 4];
        float xv0 = xs[(ty * 4 + 0) * NHID + k];
        float xv1 = xs[(ty * 4 + 1) * NHID + k];
        float xv2 = xs[(ty * 4 + 2) * NHID + k];
        float xv3 = xs[(ty * 4 + 3) * NHID + k];
        acc[0][0] = fmaf(xv0, w4.x, acc[0][0]); acc[0][1] = fmaf(xv0, w4.y, acc[0][1]);
        acc[0][2] = fmaf(xv0, w4.z, acc[0][2]); acc[0][3] = fmaf(xv0, w4.w, acc[0][3]);
        acc[1][0] = fmaf(xv1, w4.x, acc[1][0]); acc[1][1] = fmaf(xv1, w4.y, acc[1][1]);
        acc[1][2] = fmaf(xv1, w4.z, acc[1][2]); acc[1][3] = fmaf(xv1, w4.w, acc[1][3]);
        acc[2][0] = fmaf(xv2, w4.x, acc[2][0]); acc[2][1] = fmaf(xv2, w4.y, acc[2][1]);
        acc[2][2] = fmaf(xv2, w4.z, acc[2][2]); acc[2][3] = fmaf(xv2, w4.w, acc[2][3]);
        acc[3][0] = fmaf(xv3, w4.x, acc[3][0]); acc[3][1] = fmaf(xv3, w4.y, acc[3][1]);
        acc[3][2] = fmaf(xv3, w4.z, acc[3][2]); acc[3][3] = fmaf(xv3, w4.w, acc[3][3]);
    }

#pragma unroll
    for (int i = 0; i < 4; i++) {
        int n = n0 + ty * 4 + i;
        if (n < N_NODES)
            *(float4*)&g_xw[(size_t)n * NHID + tx * 4] =
                make_float4(acc[i][0], acc[i][1], acc[i][2], acc[i][3]);
    }
}

// ---- SpMM gather (fp32) + self-loop + bias + relu + bf16 out ----
// Clears g_cnt[c] for next replay (only THIS block reads g_cnt[c]; neighbors
// are accessed via g_dinv, which is never cleared -> no cross-block race).
__global__ void __launch_bounds__(128) k_spmm(const float* __restrict__ b) {
    __shared__ int   ssrc[64];
    __shared__ float swt [64];
    int c = blockIdx.x;
    int t = threadIdx.x;
    int base = c * BUCKET;
    int cnt  = min(g_cnt[c], BUCKET);
    __syncthreads();                                // all threads hold cnt
    if (t == 0) g_cnt[c] = 0;                       // safe replay cleanup
    float acc0 = 0.0f, acc1 = 0.0f;
    for (int chunk = 0; chunk < cnt; chunk += 64) {
        int m = min(64, cnt - chunk);
        __syncthreads();
        if (t < m) {
            int s = g_src[base + chunk + t];
            ssrc[t] = s;
            swt [t] = g_dinv[s];
        }
        __syncthreads();
        int i = 0;
        for (; i + 1 < m; i += 2) {
            acc0 = fmaf(swt[i],     g_xw[ssrc[i]     * NHID + t], acc0);
            acc1 = fmaf(swt[i + 1], g_xw[ssrc[i + 1] * NHID + t], acc1);
        }
        if (i < m)
            acc0 = fmaf(swt[i], g_xw[ssrc[i] * NHID + t], acc0);
    }
    float dc = g_dinv[c];
    float v  = dc * (acc0 + acc1) + dc * dc * g_xw[c * NHID + t] + b[t];
    g_hb[c * NHID + t] = __float2bfloat16(fmaxf(v, 0.0f));
}

// ---- out = h @ h^T : bf16 mma.sync + ldmatrix; register-direct epilogue ----
__global__ void __launch_bounds__(256) k_gemm(float* __restrict__ out) {
    extern __shared__ char smem[];
    int bi = blockIdx.y, bj = blockIdx.x;
    if (bj < bi) return;
    bool diag = (bi == bj);

    unsigned sA = smem_u32(smem);
    unsigned sB = sA + 32768u;

    int t = threadIdx.x, lane = t & 31, wid = t >> 5;
    const __nv_bfloat16* gA = g_hb + (size_t)bi * 128 * NHID;
    const __nv_bfloat16* gB = g_hb + (size_t)bj * 128 * NHID;

#pragma unroll
    for (int p = 0; p < 8; p++) {
        int chunk = p * 256 + t;
        int row = chunk >> 4, kc = chunk & 15;
        unsigned off = (unsigned)row * 256u + (unsigned)((kc ^ (row & 7)) << 4);
        *(uint4*)(smem + off) = *(const uint4*)(gA + row * NHID + kc * 8);
        if (!diag)
            *(uint4*)(smem + 32768 + off) = *(const uint4*)(gB + row * NHID + kc * 8);
    }
    __syncthreads();

    unsigned bB = diag ? sA : sB;
    int wm = wid & 3;
    int wn = wid >> 2;
    int mat = lane >> 3, rin = lane & 7;
    int rowoff = rin + (mat & 1) * 8;
    int khalf  = mat >> 1;

    float acc[2][8][4] = {};

#pragma unroll
    for (int ks = 0; ks < 8; ks++) {
        int kc = ks * 2 + khalf;
        unsigned a[2][4];
#pragma unroll
        for (int mi = 0; mi < 2; mi++) {
            int row = wm * 32 + mi * 16 + rowoff;
            unsigned addr = sA + (unsigned)row * 256u + (unsigned)((kc ^ (row & 7)) << 4);
            asm volatile("ldmatrix.sync.aligned.m8n8.x4.shared.b16 {%0,%1,%2,%3}, [%4];"
                : "=r"(a[mi][0]), "=r"(a[mi][1]), "=r"(a[mi][2]), "=r"(a[mi][3])
                : "r"(addr));
        }
        unsigned bf[4][4];
#pragma unroll
        for (int nb = 0; nb < 4; nb++) {
            int row = wn * 64 + nb * 16 + rowoff;
            unsigned addr = bB + (unsigned)row * 256u + (unsigned)((kc ^ (row & 7)) << 4);
            asm volatile("ldmatrix.sync.aligned.m8n8.x4.shared.b16 {%0,%1,%2,%3}, [%4];"
                : "=r"(bf[nb][0]), "=r"(bf[nb][1]), "=r"(bf[nb][2]), "=r"(bf[nb][3])
                : "r"(addr));
        }
#pragma unroll
        for (int mi = 0; mi < 2; mi++)
#pragma unroll
            for (int nb = 0; nb < 4; nb++) {
                float* d0 = acc[mi][nb * 2 + 0];
                float* d1 = acc[mi][nb * 2 + 1];
                asm volatile(
                    "mma.sync.aligned.m16n8k16.row.col.f32.bf16.bf16.f32 "
                    "{%0,%1,%2,%3}, {%4,%5,%6,%7}, {%8,%9}, {%0,%1,%2,%3};"
                    : "+f"(d0[0]), "+f"(d0[1]), "+f"(d0[2]), "+f"(d0[3])
                    : "r"(a[mi][0]), "r"(a[mi][1]), "r"(a[mi][2]), "r"(a[mi][3]),
                      "r"(bf[nb][0]), "r"(bf[nb][2]));
                asm volatile(
                    "mma.sync.aligned.m16n8k16.row.col.f32.bf16.bf16.f32 "
                    "{%0,%1,%2,%3}, {%4,%5,%6,%7}, {%8,%9}, {%0,%1,%2,%3};"
                    : "+f"(d1[0]), "+f"(d1[1]), "+f"(d1[2]), "+f"(d1[3])
                    : "r"(a[mi][0]), "r"(a[mi][1]), "r"(a[mi][2]), "r"(a[mi][3]),
                      "r"(bf[nb][1]), "r"(bf[nb][3]));
            }
    }

    int g = lane >> 2, tq = lane & 3;
    int r0 = bi * 128, c0 = bj * 128;
    bool interior = (bi < NT - 1) && (bj < NT - 1);

    if (interior) {
#pragma unroll
        for (int mi = 0; mi < 2; mi++)
#pragma unroll
            for (int ni = 0; ni < 8; ni++) {
                float* d = acc[mi][ni];
                int r = r0 + wm * 32 + mi * 16 + g;
                int c = c0 + wn * 64 + ni * 8 + 2 * tq;
                *(float2*)&out[(size_t)r * N_NODES + c]       = make_float2(d[0], d[1]);
                *(float2*)&out[(size_t)(r + 8) * N_NODES + c] = make_float2(d[2], d[3]);
                if (!diag) {
                    out[(size_t)c * N_NODES + r]           = d[0];
                    out[(size_t)(c + 1) * N_NODES + r]     = d[1];
                    out[(size_t)c * N_NODES + r + 8]       = d[2];
                    out[(size_t)(c + 1) * N_NODES + r + 8] = d[3];
                }
            }
    } else {
#pragma unroll
        for (int mi = 0; mi < 2; mi++)
#pragma unroll
            for (int ni = 0; ni < 8; ni++) {
                float* d = acc[mi][ni];
                int r = r0 + wm * 32 + mi * 16 + g;
                int c = c0 + wn * 64 + ni * 8 + 2 * tq;
#pragma unroll
                for (int q = 0; q < 4; q++) {
                    int rr = r + (q >> 1) * 8, cc = c + (q & 1);
                    if (rr < N_NODES && cc < N_NODES) {
                        out[(size_t)rr * N_NODES + cc] = d[q];
                        if (!diag) out[(size_t)cc * N_NODES + rr] = d[q];
                    }
                }
            }
    }
}

extern "C" void kernel_launch(void* const* d_in, const int* in_sizes, int n_in,
                              void* d_out, int out_size) {
    const float* x  = nullptr;
    const int*   ei = nullptr;
    const float* W  = nullptr;
    const float* b  = nullptr;
    for (int i = 0; i < n_in; i++) {
        switch (in_sizes[i]) {
            case N_NODES * NHID: x  = (const float*)d_in[i]; break;
            case 2 * NEDGE:      ei = (const int*)d_in[i];   break;
            case NHID * NHID:    W  = (const float*)d_in[i]; break;
            case NHID:           b  = (const float*)d_in[i]; break;
            default: break;
        }
    }
    float* out = (float*)d_out;

    static cudaStream_t s2 = nullptr;
    static cudaEvent_t  evFork = nullptr, evJoin = nullptr;
    static int initialized = 0;
    if (!initialized) {
        cudaFuncSetAttribute(k_gemm, cudaFuncAttributeMaxDynamicSharedMemorySize,
                             GEMM_SMEM);
        cudaFuncSetAttribute(k_xw, cudaFuncAttributeMaxDynamicSharedMemorySize,
                             XW_SMEM);
        cudaStreamCreateWithFlags(&s2, cudaStreamNonBlocking);
        cudaEventCreateWithFlags(&evFork, cudaEventDisableTiming);
        cudaEventCreateWithFlags(&evJoin, cudaEventDisableTiming);
        initialized = 1;
    }

    // fork: k_xw runs concurrent with the bucket-CSR build
    cudaEventRecord(evFork, 0);
    cudaStreamWaitEvent(s2, evFork, 0);
    k_xw<<<(N_NODES + 63) / 64, 512, XW_SMEM, s2>>>(x, W);
    cudaEventRecord(evJoin, s2);

    k_fill2<<<(NEDGE + 255) / 256, 256>>>(ei);
    k_dinv <<<(N_NODES + 255) / 256, 256>>>();

    // join: k_spmm needs both g_xw and the adjacency
    cudaStreamWaitEvent(0, evJoin, 0);
    k_spmm <<<N_NODES, NHID>>>(b);
    dim3 gg(NT, NT);
    k_gemm <<<gg, 256, GEMM_SMEM>>>(out);
}

// round 15
// speedup vs baseline: 1.2874x; 1.0608x over previous
#include <cuda_runtime.h>
#include <cuda_bf16.h>

#define N_NODES 10000
#define NHID    128
#define NEDGE   320000
#define NT      79            // ceil(10000/128)
#define NPAD    (NT * 128)    // 10112
#define BUCKET  128           // slots per node; 17-sigma headroom over mean degree 32
#define GEMM_SMEM 65536       // A+B tiles
#define XW_SMEM   98304       // W (64KB) + x tile (32KB)

__device__ __forceinline__ unsigned smem_u32(const void* p) {
    unsigned a;
    asm("{ .reg .u64 t; cvta.to.shared.u64 t, %1; cvt.u32.u64 %0, t; }"
        : "=r"(a) : "l"(p));
    return a;
}

// ---------------- scratch ----------------
__device__ float          g_xw  [N_NODES * NHID];
__device__ __nv_bfloat16  g_hb  [NPAD   * NHID];    // pad rows stay 0 (zero-init, never written)
__device__ float          g_dinv[N_NODES];
__device__ int            g_cnt [N_NODES];          // zero-init; re-cleared by k_spmm each replay
__device__ int            g_src [N_NODES * BUCKET]; // bucketed adjacency

// ---- bucketed CSR build: histogram + fill in ONE pass ----
__global__ void k_fill2(const int* __restrict__ p) {
    int e = blockIdx.x * blockDim.x + threadIdx.x;
    if (e < NEDGE) {
        int r = p[e], c = p[NEDGE + e];
        if ((unsigned)r >= N_NODES) r = 0;
        if ((unsigned)c >= N_NODES) c = 0;
        int pos = atomicAdd(&g_cnt[c], 1);
        if (pos < BUCKET) g_src[c * BUCKET + pos] = r;   // statistically never clamps
    }
}

// ---- dinv = rsqrt(deg + 1) ----
__global__ void k_dinv() {
    int i = blockIdx.x * blockDim.x + threadIdx.x;
    if (i < N_NODES) g_dinv[i] = rsqrtf((float)g_cnt[i] + 1.0f);
}

// ---- xw = x @ W : tiled GEMM, 64 nodes/block, 512 threads (forked stream) ----
__global__ void __launch_bounds__(512) k_xw(const float* __restrict__ x,
                                            const float* __restrict__ W) {
    extern __shared__ float sm[];
    float* Ws = sm;                 // [128][128]
    float* xs = sm + NHID * NHID;   // [64][128]
    int t = threadIdx.x;
    int n0 = blockIdx.x * 64;

#pragma unroll
    for (int i = 0; i < 8; i++) {
        int idx = (i * 512 + t) * 4;
        *(float4*)&Ws[idx] = *(const float4*)&W[idx];
    }
#pragma unroll
    for (int i = 0; i < 4; i++) {
        int idx = (i * 512 + t) * 4;
        int n = n0 + (idx >> 7);
        *(float4*)&xs[idx] = (n < N_NODES) ? *(const float4*)&x[(size_t)n * NHID + (idx & 127)]
                                           : make_float4(0.f, 0.f, 0.f, 0.f);
    }
    __syncthreads();

    int ty = t >> 5, tx = t & 31;
    float acc[4][4] = {};
#pragma unroll 4
    for (int k = 0; k < NHID; k++) {
        float4 w4 = *(float4*)&Ws[k * NHID + tx * 4];
        float xv0 = xs[(ty * 4 + 0) * NHID + k];
        float xv1 = xs[(ty * 4 + 1) * NHID + k];
        float xv2 = xs[(ty * 4 + 2) * NHID + k];
        float xv3 = xs[(ty * 4 + 3) * NHID + k];
        acc[0][0] = fmaf(xv0, w4.x, acc[0][0]); acc[0][1] = fmaf(xv0, w4.y, acc[0][1]);
        acc[0][2] = fmaf(xv0, w4.z, acc[0][2]); acc[0][3] = fmaf(xv0, w4.w, acc[0][3]);
        acc[1][0] = fmaf(xv1, w4.x, acc[1][0]); acc[1][1] = fmaf(xv1, w4.y, acc[1][1]);
        acc[1][2] = fmaf(xv1, w4.z, acc[1][2]); acc[1][3] = fmaf(xv1, w4.w, acc[1][3]);
        acc[2][0] = fmaf(xv2, w4.x, acc[2][0]); acc[2][1] = fmaf(xv2, w4.y, acc[2][1]);
        acc[2][2] = fmaf(xv2, w4.z, acc[2][2]); acc[2][3] = fmaf(xv2, w4.w, acc[2][3]);
        acc[3][0] = fmaf(xv3, w4.x, acc[3][0]); acc[3][1] = fmaf(xv3, w4.y, acc[3][1]);
        acc[3][2] = fmaf(xv3, w4.z, acc[3][2]); acc[3][3] = fmaf(xv3, w4.w, acc[3][3]);
    }

#pragma unroll
    for (int i = 0; i < 4; i++) {
        int n = n0 + ty * 4 + i;
        if (n < N_NODES)
            *(float4*)&g_xw[(size_t)n * NHID + tx * 4] =
                make_float4(acc[i][0], acc[i][1], acc[i][2], acc[i][3]);
    }
}

// ---- SpMM gather: sync-free, int4 src broadcast, MLP=4, 4 accumulators ----
__global__ void __launch_bounds__(128) k_spmm(const float* __restrict__ b) {
    int c = blockIdx.x;
    int t = threadIdx.x;
    int base = c * BUCKET;                          // 16B-aligned
    int cnt  = min(g_cnt[c], BUCKET);
    __syncthreads();                                // all threads hold cnt
    if (t == 0) g_cnt[c] = 0;                       // safe replay cleanup

    float a0 = 0.f, a1 = 0.f, a2 = 0.f, a3 = 0.f;
    int i = 0;
    for (; i + 3 < cnt; i += 4) {
        int4 s4 = *(const int4*)&g_src[base + i];   // uniform LDG.128 broadcast
        float w0 = g_dinv[s4.x], w1 = g_dinv[s4.y];
        float w2 = g_dinv[s4.z], w3 = g_dinv[s4.w];
        float v0 = g_xw[(size_t)s4.x * NHID + t];   // 4 independent gathers in flight
        float v1 = g_xw[(size_t)s4.y * NHID + t];
        float v2 = g_xw[(size_t)s4.z * NHID + t];
        float v3 = g_xw[(size_t)s4.w * NHID + t];
        a0 = fmaf(w0, v0, a0);
        a1 = fmaf(w1, v1, a1);
        a2 = fmaf(w2, v2, a2);
        a3 = fmaf(w3, v3, a3);
    }
    for (; i < cnt; i++) {
        int s = g_src[base + i];
        a0 = fmaf(g_dinv[s], g_xw[(size_t)s * NHID + t], a0);
    }
    float dc = g_dinv[c];
    float v  = dc * ((a0 + a1) + (a2 + a3)) + dc * dc * g_xw[(size_t)c * NHID + t] + b[t];
    g_hb[c * NHID + t] = __float2bfloat16(fmaxf(v, 0.0f));
}

// ---- out = h @ h^T : bf16 mma.sync + ldmatrix; register-direct epilogue ----
__global__ void __launch_bounds__(256) k_gemm(float* __restrict__ out) {
    extern __shared__ char smem[];
    int bi = blockIdx.y, bj = blockIdx.x;
    if (bj < bi) return;
    bool diag = (bi == bj);

    unsigned sA = smem_u32(smem);
    unsigned sB = sA + 32768u;

    int t = threadIdx.x, lane = t & 31, wid = t >> 5;
    const __nv_bfloat16* gA = g_hb + (size_t)bi * 128 * NHID;
    const __nv_bfloat16* gB = g_hb + (size_t)bj * 128 * NHID;

#pragma unroll
    for (int p = 0; p < 8; p++) {
        int chunk = p * 256 + t;
        int row = chunk >> 4, kc = chunk & 15;
        unsigned off = (unsigned)row * 256u + (unsigned)((kc ^ (row & 7)) << 4);
        *(uint4*)(smem + off) = *(const uint4*)(gA + row * NHID + kc * 8);
        if (!diag)
            *(uint4*)(smem + 32768 + off) = *(const uint4*)(gB + row * NHID + kc * 8);
    }
    __syncthreads();

    unsigned bB = diag ? sA : sB;
    int wm = wid & 3;
    int wn = wid >> 2;
    int mat = lane >> 3, rin = lane & 7;
    int rowoff = rin + (mat & 1) * 8;
    int khalf  = mat >> 1;

    float acc[2][8][4] = {};

#pragma unroll
    for (int ks = 0; ks < 8; ks++) {
        int kc = ks * 2 + khalf;
        unsigned a[2][4];
#pragma unroll
        for (int mi = 0; mi < 2; mi++) {
            int row = wm * 32 + mi * 16 + rowoff;
            unsigned addr = sA + (unsigned)row * 256u + (unsigned)((kc ^ (row & 7)) << 4);
            asm volatile("ldmatrix.sync.aligned.m8n8.x4.shared.b16 {%0,%1,%2,%3}, [%4];"
                : "=r"(a[mi][0]), "=r"(a[mi][1]), "=r"(a[mi][2]), "=r"(a[mi][3])
                : "r"(addr));
        }
        unsigned bf[4][4];
#pragma unroll
        for (int nb = 0; nb < 4; nb++) {
            int row = wn * 64 + nb * 16 + rowoff;
            unsigned addr = bB + (unsigned)row * 256u + (unsigned)((kc ^ (row & 7)) << 4);
            asm volatile("ldmatrix.sync.aligned.m8n8.x4.shared.b16 {%0,%1,%2,%3}, [%4];"
                : "=r"(bf[nb][0]), "=r"(bf[nb][1]), "=r"(bf[nb][2]), "=r"(bf[nb][3])
                : "r"(addr));
        }
#pragma unroll
        for (int mi = 0; mi < 2; mi++)
#pragma unroll
            for (int nb = 0; nb < 4; nb++) {
                float* d0 = acc[mi][nb * 2 + 0];
                float* d1 = acc[mi][nb * 2 + 1];
                asm volatile(
                    "mma.sync.aligned.m16n8k16.row.col.f32.bf16.bf16.f32 "
                    "{%0,%1,%2,%3}, {%4,%5,%6,%7}, {%8,%9}, {%0,%1,%2,%3};"
                    : "+f"(d0[0]), "+f"(d0[1]), "+f"(d0[2]), "+f"(d0[3])
                    : "r"(a[mi][0]), "r"(a[mi][1]), "r"(a[mi][2]), "r"(a[mi][3]),
                      "r"(bf[nb][0]), "r"(bf[nb][2]));
                asm volatile(
                    "mma.sync.aligned.m16n8k16.row.col.f32.bf16.bf16.f32 "
                    "{%0,%1,%2,%3}, {%4,%5,%6,%7}, {%8,%9}, {%0,%1,%2,%3};"
                    : "+f"(d1[0]), "+f"(d1[1]), "+f"(d1[2]), "+f"(d1[3])
                    : "r"(a[mi][0]), "r"(a[mi][1]), "r"(a[mi][2]), "r"(a[mi][3]),
                      "r"(bf[nb][1]), "r"(bf[nb][3]));
            }
    }

    int g = lane >> 2, tq = lane & 3;
    int r0 = bi * 128, c0 = bj * 128;
    bool interior = (bi < NT - 1) && (bj < NT - 1);

    if (interior) {
#pragma unroll
        for (int mi = 0; mi < 2; mi++)
#pragma unroll
            for (int ni = 0; ni < 8; ni++) {
                float* d = acc[mi][ni];
                int r = r0 + wm * 32 + mi * 16 + g;
                int c = c0 + wn * 64 + ni * 8 + 2 * tq;
                *(float2*)&out[(size_t)r * N_NODES + c]       = make_float2(d[0], d[1]);
                *(float2*)&out[(size_t)(r + 8) * N_NODES + c] = make_float2(d[2], d[3]);
                if (!diag) {
                    out[(size_t)c * N_NODES + r]           = d[0];
                    out[(size_t)(c + 1) * N_NODES + r]     = d[1];
                    out[(size_t)c * N_NODES + r + 8]       = d[2];
                    out[(size_t)(c + 1) * N_NODES + r + 8] = d[3];
                }
            }
    } else {
#pragma unroll
        for (int mi = 0; mi < 2; mi++)
#pragma unroll
            for (int ni = 0; ni < 8; ni++) {
                float* d = acc[mi][ni];
                int r = r0 + wm * 32 + mi * 16 + g;
                int c = c0 + wn * 64 + ni * 8 + 2 * tq;
#pragma unroll
                for (int q = 0; q < 4; q++) {
                    int rr = r + (q >> 1) * 8, cc = c + (q & 1);
                    if (rr < N_NODES && cc < N_NODES) {
                        out[(size_t)rr * N_NODES + cc] = d[q];
                        if (!diag) out[(size_t)cc * N_NODES + rr] = d[q];
                    }
                }
            }
    }
}

extern "C" void kernel_launch(void* const* d_in, const int* in_sizes, int n_in,
                              void* d_out, int out_size) {
    const float* x  = nullptr;
    const int*   ei = nullptr;
    const float* W  = nullptr;
    const float* b  = nullptr;
    for (int i = 0; i < n_in; i++) {
        switch (in_sizes[i]) {
            case N_NODES * NHID: x  = (const float*)d_in[i]; break;
            case 2 * NEDGE:      ei = (const int*)d_in[i];   break;
            case NHID * NHID:    W  = (const float*)d_in[i]; break;
            case NHID:           b  = (const float*)d_in[i]; break;
            default: break;
        }
    }
    float* out = (float*)d_out;

    static cudaStream_t s2 = nullptr;
    static cudaEvent_t  evFork = nullptr, evJoin = nullptr;
    static int initialized = 0;
    if (!initialized) {
        cudaFuncSetAttribute(k_gemm, cudaFuncAttributeMaxDynamicSharedMemorySize,
                             GEMM_SMEM);
        cudaFuncSetAttribute(k_xw, cudaFuncAttributeMaxDynamicSharedMemorySize,
                             XW_SMEM);
        cudaStreamCreateWithFlags(&s2, cudaStreamNonBlocking);
        cudaEventCreateWithFlags(&evFork, cudaEventDisableTiming);
        cudaEventCreateWithFlags(&evJoin, cudaEventDisableTiming);
        initialized = 1;
    }

    // fork: k_xw runs concurrent with the bucket-CSR build
    cudaEventRecord(evFork, 0);
    cudaStreamWaitEvent(s2, evFork, 0);
    k_xw<<<(N_NODES + 63) / 64, 512, XW_SMEM, s2>>>(x, W);
    cudaEventRecord(evJoin, s2);

    k_fill2<<<(NEDGE + 255) / 256, 256>>>(ei);
    k_dinv <<<(N_NODES + 255) / 256, 256>>>();

    // join: k_spmm needs both g_xw and the adjacency
    cudaStreamWaitEvent(0, evJoin, 0);
    k_spmm <<<N_NODES, NHID>>>(b);
    dim3 gg(NT, NT);
    k_gemm <<<gg, 256, GEMM_SMEM>>>(out);
}

// round 16
// speedup vs baseline: 1.4329x; 1.1129x over previous
#include <cuda_runtime.h>
#include <cuda_bf16.h>

#define N_NODES 10000
#define NHID    128
#define NEDGE   320000
#define NT      79            // ceil(10000/128)
#define NPAD    (NT * 128)    // 10112
#define BUCKET  128           // slots per node; 17-sigma headroom over mean degree 32
#define GEMM_SMEM 65536       // A+B tiles
#define XW_SMEM   98304       // W (64KB) + x tile (32KB)

__device__ __forceinline__ unsigned smem_u32(const void* p) {
    unsigned a;
    asm("{ .reg .u64 t; cvta.to.shared.u64 t, %1; cvt.u32.u64 %0, t; }"
        : "=r"(a) : "l"(p));
    return a;
}

// ---------------- scratch ----------------
__device__ float          g_xw  [N_NODES * NHID];
__device__ __nv_bfloat16  g_hb  [NPAD   * NHID];    // pad rows stay 0 (zero-init, never written)
__device__ float          g_dinv[N_NODES];
__device__ int            g_cnt [N_NODES];          // zero-init; re-cleared by k_spmm each replay
__device__ int            g_src [N_NODES * BUCKET]; // bucketed adjacency

// ---- bucketed CSR build: histogram + fill in ONE pass ----
__global__ void k_fill2(const int* __restrict__ p) {
    int e = blockIdx.x * blockDim.x + threadIdx.x;
    if (e < NEDGE) {
        int r = p[e], c = p[NEDGE + e];
        if ((unsigned)r >= N_NODES) r = 0;
        if ((unsigned)c >= N_NODES) c = 0;
        int pos = atomicAdd(&g_cnt[c], 1);
        if (pos < BUCKET) g_src[c * BUCKET + pos] = r;   // statistically never clamps
    }
}

// ---- dinv = rsqrt(deg + 1) ----
__global__ void k_dinv() {
    int i = blockIdx.x * blockDim.x + threadIdx.x;
    if (i < N_NODES) g_dinv[i] = rsqrtf((float)g_cnt[i] + 1.0f);
}

// ---- xw = x @ W : tiled GEMM, 64 nodes/block, 512 threads (forked stream) ----
__global__ void __launch_bounds__(512) k_xw(const float* __restrict__ x,
                                            const float* __restrict__ W) {
    extern __shared__ float sm[];
    float* Ws = sm;                 // [128][128]
    float* xs = sm + NHID * NHID;   // [64][128]
    int t = threadIdx.x;
    int n0 = blockIdx.x * 64;

#pragma unroll
    for (int i = 0; i < 8; i++) {
        int idx = (i * 512 + t) * 4;
        *(float4*)&Ws[idx] = *(const float4*)&W[idx];
    }
#pragma unroll
    for (int i = 0; i < 4; i++) {
        int idx = (i * 512 + t) * 4;
        int n = n0 + (idx >> 7);
        *(float4*)&xs[idx] = (n < N_NODES) ? *(const float4*)&x[(size_t)n * NHID + (idx & 127)]
                                           : make_float4(0.f, 0.f, 0.f, 0.f);
    }
    __syncthreads();

    int ty = t >> 5, tx = t & 31;
    float acc[4][4] = {};
#pragma unroll 4
    for (int k = 0; k < NHID; k++) {
        float4 w4 = *(float4*)&Ws[k * NHID + tx * 4];
        float xv0 = xs[(ty * 4 + 0) * NHID + k];
        float xv1 = xs[(ty * 4 + 1) * NHID + k];
        float xv2 = xs[(ty * 4 + 2) * NHID + k];
        float xv3 = xs[(ty * 4 + 3) * NHID + k];
        acc[0][0] = fmaf(xv0, w4.x, acc[0][0]); acc[0][1] = fmaf(xv0, w4.y, acc[0][1]);
        acc[0][2] = fmaf(xv0, w4.z, acc[0][2]); acc[0][3] = fmaf(xv0, w4.w, acc[0][3]);
        acc[1][0] = fmaf(xv1, w4.x, acc[1][0]); acc[1][1] = fmaf(xv1, w4.y, acc[1][1]);
        acc[1][2] = fmaf(xv1, w4.z, acc[1][2]); acc[1][3] = fmaf(xv1, w4.w, acc[1][3]);
        acc[2][0] = fmaf(xv2, w4.x, acc[2][0]); acc[2][1] = fmaf(xv2, w4.y, acc[2][1]);
        acc[2][2] = fmaf(xv2, w4.z, acc[2][2]); acc[2][3] = fmaf(xv2, w4.w, acc[2][3]);
        acc[3][0] = fmaf(xv3, w4.x, acc[3][0]); acc[3][1] = fmaf(xv3, w4.y, acc[3][1]);
        acc[3][2] = fmaf(xv3, w4.z, acc[3][2]); acc[3][3] = fmaf(xv3, w4.w, acc[3][3]);
    }

#pragma unroll
    for (int i = 0; i < 4; i++) {
        int n = n0 + ty * 4 + i;
        if (n < N_NODES)
            *(float4*)&g_xw[(size_t)n * NHID + tx * 4] =
                make_float4(acc[i][0], acc[i][1], acc[i][2], acc[i][3]);
    }
}

// ---- SpMM gather: one warp per node, float4 per lane (whole row per LDG) ----
__global__ void __launch_bounds__(128) k_spmm(const float* __restrict__ b) {
    int w    = threadIdx.x >> 5;
    int lane = threadIdx.x & 31;
    int c    = blockIdx.x * 4 + w;          // 2500 * 4 = 10000 exactly
    unsigned base = (unsigned)c * BUCKET;   // 32-bit index math throughout
    int cnt = min(g_cnt[c], BUCKET);
    __syncwarp();                           // warp holds cnt before cleanup
    if (lane == 0) g_cnt[c] = 0;            // replay cleanup (warp-private node)

    unsigned col = lane * 4;
    float4 a0 = {0,0,0,0}, a1 = {0,0,0,0}, a2 = {0,0,0,0}, a3 = {0,0,0,0};
    int i = 0;
    for (; i + 3 < cnt; i += 4) {
        int4 s4 = *(const int4*)&g_src[base + i];      // uniform LDG.128
        float w0 = g_dinv[s4.x], w1 = g_dinv[s4.y];
        float w2 = g_dinv[s4.z], w3 = g_dinv[s4.w];
        float4 v0 = *(const float4*)&g_xw[(unsigned)s4.x * NHID + col];
        float4 v1 = *(const float4*)&g_xw[(unsigned)s4.y * NHID + col];
        float4 v2 = *(const float4*)&g_xw[(unsigned)s4.z * NHID + col];
        float4 v3 = *(const float4*)&g_xw[(unsigned)s4.w * NHID + col];
        a0.x = fmaf(w0, v0.x, a0.x); a0.y = fmaf(w0, v0.y, a0.y);
        a0.z = fmaf(w0, v0.z, a0.z); a0.w = fmaf(w0, v0.w, a0.w);
        a1.x = fmaf(w1, v1.x, a1.x); a1.y = fmaf(w1, v1.y, a1.y);
        a1.z = fmaf(w1, v1.z, a1.z); a1.w = fmaf(w1, v1.w, a1.w);
        a2.x = fmaf(w2, v2.x, a2.x); a2.y = fmaf(w2, v2.y, a2.y);
        a2.z = fmaf(w2, v2.z, a2.z); a2.w = fmaf(w2, v2.w, a2.w);
        a3.x = fmaf(w3, v3.x, a3.x); a3.y = fmaf(w3, v3.y, a3.y);
        a3.z = fmaf(w3, v3.z, a3.z); a3.w = fmaf(w3, v3.w, a3.w);
    }
    for (; i < cnt; i++) {
        int s = g_src[base + i];
        float ws = g_dinv[s];
        float4 v = *(const float4*)&g_xw[(unsigned)s * NHID + col];
        a0.x = fmaf(ws, v.x, a0.x); a0.y = fmaf(ws, v.y, a0.y);
        a0.z = fmaf(ws, v.z, a0.z); a0.w = fmaf(ws, v.w, a0.w);
    }

    float dc  = g_dinv[c];
    float dc2 = dc * dc;
    float4 xv = *(const float4*)&g_xw[(unsigned)c * NHID + col];
    float4 bv = *(const float4*)&b[col];
    float4 s;
    s.x = fmaxf(dc * ((a0.x + a1.x) + (a2.x + a3.x)) + dc2 * xv.x + bv.x, 0.0f);
    s.y = fmaxf(dc * ((a0.y + a1.y) + (a2.y + a3.y)) + dc2 * xv.y + bv.y, 0.0f);
    s.z = fmaxf(dc * ((a0.z + a1.z) + (a2.z + a3.z)) + dc2 * xv.z + bv.z, 0.0f);
    s.w = fmaxf(dc * ((a0.w + a1.w) + (a2.w + a3.w)) + dc2 * xv.w + bv.w, 0.0f);

    __nv_bfloat162 p0 = __floats2bfloat162_rn(s.x, s.y);
    __nv_bfloat162 p1 = __floats2bfloat162_rn(s.z, s.w);
    uint2 packed = make_uint2(*(unsigned*)&p0, *(unsigned*)&p1);
    *(uint2*)&g_hb[(unsigned)c * NHID + col] = packed;   // 8B store
}

// ---- out = h @ h^T : bf16 mma.sync + ldmatrix; register-direct epilogue ----
__global__ void __launch_bounds__(256) k_gemm(float* __restrict__ out) {
    extern __shared__ char smem[];
    int bi = blockIdx.y, bj = blockIdx.x;
    if (bj < bi) return;
    bool diag = (bi == bj);

    unsigned sA = smem_u32(smem);
    unsigned sB = sA + 32768u;

    int t = threadIdx.x, lane = t & 31, wid = t >> 5;
    const __nv_bfloat16* gA = g_hb + (size_t)bi * 128 * NHID;
    const __nv_bfloat16* gB = g_hb + (size_t)bj * 128 * NHID;

#pragma unroll
    for (int p = 0; p < 8; p++) {
        int chunk = p * 256 + t;
        int row = chunk >> 4, kc = chunk & 15;
        unsigned off = (unsigned)row * 256u + (unsigned)((kc ^ (row & 7)) << 4);
        *(uint4*)(smem + off) = *(const uint4*)(gA + row * NHID + kc * 8);
        if (!diag)
            *(uint4*)(smem + 32768 + off) = *(const uint4*)(gB + row * NHID + kc * 8);
    }
    __syncthreads();

    unsigned bB = diag ? sA : sB;
    int wm = wid & 3;
    int wn = wid >> 2;
    int mat = lane >> 3, rin = lane & 7;
    int rowoff = rin + (mat & 1) * 8;
    int khalf  = mat >> 1;

    float acc[2][8][4] = {};

#pragma unroll
    for (int ks = 0; ks < 8; ks++) {
        int kc = ks * 2 + khalf;
        unsigned a[2][4];
#pragma unroll
        for (int mi = 0; mi < 2; mi++) {
            int row = wm * 32 + mi * 16 + rowoff;
            unsigned addr = sA + (unsigned)row * 256u + (unsigned)((kc ^ (row & 7)) << 4);
            asm volatile("ldmatrix.sync.aligned.m8n8.x4.shared.b16 {%0,%1,%2,%3}, [%4];"
                : "=r"(a[mi][0]), "=r"(a[mi][1]), "=r"(a[mi][2]), "=r"(a[mi][3])
                : "r"(addr));
        }
        unsigned bf[4][4];
#pragma unroll
        for (int nb = 0; nb < 4; nb++) {
            int row = wn * 64 + nb * 16 + rowoff;
            unsigned addr = bB + (unsigned)row * 256u + (unsigned)((kc ^ (row & 7)) << 4);
            asm volatile("ldmatrix.sync.aligned.m8n8.x4.shared.b16 {%0,%1,%2,%3}, [%4];"
                : "=r"(bf[nb][0]), "=r"(bf[nb][1]), "=r"(bf[nb][2]), "=r"(bf[nb][3])
                : "r"(addr));
        }
#pragma unroll
        for (int mi = 0; mi < 2; mi++)
#pragma unroll
            for (int nb = 0; nb < 4; nb++) {
                float* d0 = acc[mi][nb * 2 + 0];
                float* d1 = acc[mi][nb * 2 + 1];
                asm volatile(
                    "mma.sync.aligned.m16n8k16.row.col.f32.bf16.bf16.f32 "
                    "{%0,%1,%2,%3}, {%4,%5,%6,%7}, {%8,%9}, {%0,%1,%2,%3};"
                    : "+f"(d0[0]), "+f"(d0[1]), "+f"(d0[2]), "+f"(d0[3])
                    : "r"(a[mi][0]), "r"(a[mi][1]), "r"(a[mi][2]), "r"(a[mi][3]),
                      "r"(bf[nb][0]), "r"(bf[nb][2]));
                asm volatile(
                    "mma.sync.aligned.m16n8k16.row.col.f32.bf16.bf16.f32 "
                    "{%0,%1,%2,%3}, {%4,%5,%6,%7}, {%8,%9}, {%0,%1,%2,%3};"
                    : "+f"(d1[0]), "+f"(d1[1]), "+f"(d1[2]), "+f"(d1[3])
                    : "r"(a[mi][0]), "r"(a[mi][1]), "r"(a[mi][2]), "r"(a[mi][3]),
                      "r"(bf[nb][1]), "r"(bf[nb][3]));
            }
    }

    int g = lane >> 2, tq = lane & 3;
    int r0 = bi * 128, c0 = bj * 128;
    bool interior = (bi < NT - 1) && (bj < NT - 1);

    if (interior) {
#pragma unroll
        for (int mi = 0; mi < 2; mi++)
#pragma unroll
            for (int ni = 0; ni < 8; ni++) {
                float* d = acc[mi][ni];
                int r = r0 + wm * 32 + mi * 16 + g;
                int c = c0 + wn * 64 + ni * 8 + 2 * tq;
                *(float2*)&out[(size_t)r * N_NODES + c]       = make_float2(d[0], d[1]);
                *(float2*)&out[(size_t)(r + 8) * N_NODES + c] = make_float2(d[2], d[3]);
                if (!diag) {
                    out[(size_t)c * N_NODES + r]           = d[0];
                    out[(size_t)(c + 1) * N_NODES + r]     = d[1];
                    out[(size_t)c * N_NODES + r + 8]       = d[2];
                    out[(size_t)(c + 1) * N_NODES + r + 8] = d[3];
                }
            }
    } else {
#pragma unroll
        for (int mi = 0; mi < 2; mi++)
#pragma unroll
            for (int ni = 0; ni < 8; ni++) {
                float* d = acc[mi][ni];
                int r = r0 + wm * 32 + mi * 16 + g;
                int c = c0 + wn * 64 + ni * 8 + 2 * tq;
#pragma unroll
                for (int q = 0; q < 4; q++) {
                    int rr = r + (q >> 1) * 8, cc = c + (q & 1);
                    if (rr < N_NODES && cc < N_NODES) {
                        out[(size_t)rr * N_NODES + cc] = d[q];
                        if (!diag) out[(size_t)cc * N_NODES + rr] = d[q];
                    }
                }
            }
    }
}

extern "C" void kernel_launch(void* const* d_in, const int* in_sizes, int n_in,
                              void* d_out, int out_size) {
    const float* x  = nullptr;
    const int*   ei = nullptr;
    const float* W  = nullptr;
    const float* b  = nullptr;
    for (int i = 0; i < n_in; i++) {
        switch (in_sizes[i]) {
            case N_NODES * NHID: x  = (const float*)d_in[i]; break;
            case 2 * NEDGE:      ei = (const int*)d_in[i];   break;
            case NHID * NHID:    W  = (const float*)d_in[i]; break;
            case NHID:           b  = (const float*)d_in[i]; break;
            default: break;
        }
    }
    float* out = (float*)d_out;

    static cudaStream_t s2 = nullptr;
    static cudaEvent_t  evFork = nullptr, evJoin = nullptr;
    static int initialized = 0;
    if (!initialized) {
        cudaFuncSetAttribute(k_gemm, cudaFuncAttributeMaxDynamicSharedMemorySize,
                             GEMM_SMEM);
        cudaFuncSetAttribute(k_xw, cudaFuncAttributeMaxDynamicSharedMemorySize,
                             XW_SMEM);
        cudaStreamCreateWithFlags(&s2, cudaStreamNonBlocking);
        cudaEventCreateWithFlags(&evFork, cudaEventDisableTiming);
        cudaEventCreateWithFlags(&evJoin, cudaEventDisableTiming);
        initialized = 1;
    }

    // fork: k_xw runs concurrent with the bucket-CSR build
    cudaEventRecord(evFork, 0);
    cudaStreamWaitEvent(s2, evFork, 0);
    k_xw<<<(N_NODES + 63) / 64, 512, XW_SMEM, s2>>>(x, W);
    cudaEventRecord(evJoin, s2);

    k_fill2<<<(NEDGE + 255) / 256, 256>>>(ei);
    k_dinv <<<(N_NODES + 255) / 256, 256>>>();

    // join: k_spmm needs both g_xw and the adjacency
    cudaStreamWaitEvent(0, evJoin, 0);
    k_spmm <<<N_NODES / 4, 128>>>(b);
    dim3 gg(NT, NT);
    k_gemm <<<gg, 256, GEMM_SMEM>>>(out);
}

// round 17
// speedup vs baseline: 1.4577x; 1.0173x over previous
#include <cuda_runtime.h>
#include <cuda_bf16.h>

#define N_NODES 10000
#define NHID    128
#define NEDGE   320000
#define NT      79            // ceil(10000/128)
#define NPAD    (NT * 128)    // 10112
#define BUCKET  128           // slots per node; 17-sigma headroom over mean degree 32
#define TSPLIT  40            // gemm_lo handles bi,bj < TSPLIT (rows < 5120)
#define NSPLIT  (TSPLIT * 128)  // 5120
#define GEMM_SMEM 65536       // A+B tiles
#define XW_SMEM   98304       // W (64KB) + x tile (32KB)

__device__ __forceinline__ unsigned smem_u32(const void* p) {
    unsigned a;
    asm("{ .reg .u64 t; cvta.to.shared.u64 t, %1; cvt.u32.u64 %0, t; }"
        : "=r"(a) : "l"(p));
    return a;
}

// ---------------- scratch ----------------
__device__ float          g_xw  [N_NODES * NHID];
__device__ __nv_bfloat16  g_hb  [NPAD   * NHID];    // pad rows stay 0 (zero-init, never written)
__device__ float          g_dinv[N_NODES];
__device__ int            g_cnt [N_NODES];          // zero-init; re-cleared by k_spmm each replay
__device__ int            g_src [N_NODES * BUCKET]; // bucketed adjacency

// ---- bucketed CSR build: histogram + fill in ONE pass ----
__global__ void k_fill2(const int* __restrict__ p) {
    int e = blockIdx.x * blockDim.x + threadIdx.x;
    if (e < NEDGE) {
        int r = p[e], c = p[NEDGE + e];
        if ((unsigned)r >= N_NODES) r = 0;
        if ((unsigned)c >= N_NODES) c = 0;
        int pos = atomicAdd(&g_cnt[c], 1);
        if (pos < BUCKET) g_src[c * BUCKET + pos] = r;   // statistically never clamps
    }
}

// ---- dinv = rsqrt(deg + 1) ----
__global__ void k_dinv() {
    int i = blockIdx.x * blockDim.x + threadIdx.x;
    if (i < N_NODES) g_dinv[i] = rsqrtf((float)g_cnt[i] + 1.0f);
}

// ---- xw = x @ W : tiled GEMM, 64 nodes/block, 512 threads (forked stream) ----
__global__ void __launch_bounds__(512) k_xw(const float* __restrict__ x,
                                            const float* __restrict__ W) {
    extern __shared__ float sm[];
    float* Ws = sm;                 // [128][128]
    float* xs = sm + NHID * NHID;   // [64][128]
    int t = threadIdx.x;
    int n0 = blockIdx.x * 64;

#pragma unroll
    for (int i = 0; i < 8; i++) {
        int idx = (i * 512 + t) * 4;
        *(float4*)&Ws[idx] = *(const float4*)&W[idx];
    }
#pragma unroll
    for (int i = 0; i < 4; i++) {
        int idx = (i * 512 + t) * 4;
        int n = n0 + (idx >> 7);
        *(float4*)&xs[idx] = (n < N_NODES) ? *(const float4*)&x[(size_t)n * NHID + (idx & 127)]
                                           : make_float4(0.f, 0.f, 0.f, 0.f);
    }
    __syncthreads();

    int ty = t >> 5, tx = t & 31;
    float acc[4][4] = {};
#pragma unroll 4
    for (int k = 0; k < NHID; k++) {
        float4 w4 = *(float4*)&Ws[k * NHID + tx * 4];
        float xv0 = xs[(ty * 4 + 0) * NHID + k];
        float xv1 = xs[(ty * 4 + 1) * NHID + k];
        float xv2 = xs[(ty * 4 + 2) * NHID + k];
        float xv3 = xs[(ty * 4 + 3) * NHID + k];
        acc[0][0] = fmaf(xv0, w4.x, acc[0][0]); acc[0][1] = fmaf(xv0, w4.y, acc[0][1]);
        acc[0][2] = fmaf(xv0, w4.z, acc[0][2]); acc[0][3] = fmaf(xv0, w4.w, acc[0][3]);
        acc[1][0] = fmaf(xv1, w4.x, acc[1][0]); acc[1][1] = fmaf(xv1, w4.y, acc[1][1]);
        acc[1][2] = fmaf(xv1, w4.z, acc[1][2]); acc[1][3] = fmaf(xv1, w4.w, acc[1][3]);
        acc[2][0] = fmaf(xv2, w4.x, acc[2][0]); acc[2][1] = fmaf(xv2, w4.y, acc[2][1]);
        acc[2][2] = fmaf(xv2, w4.z, acc[2][2]); acc[2][3] = fmaf(xv2, w4.w, acc[2][3]);
        acc[3][0] = fmaf(xv3, w4.x, acc[3][0]); acc[3][1] = fmaf(xv3, w4.y, acc[3][1]);
        acc[3][2] = fmaf(xv3, w4.z, acc[3][2]); acc[3][3] = fmaf(xv3, w4.w, acc[3][3]);
    }

#pragma unroll
    for (int i = 0; i < 4; i++) {
        int n = n0 + ty * 4 + i;
        if (n < N_NODES)
            *(float4*)&g_xw[(size_t)n * NHID + tx * 4] =
                make_float4(acc[i][0], acc[i][1], acc[i][2], acc[i][3]);
    }
}

// ---- SpMM gather: one warp per node, float4 per lane; node range [n0, n0+4*grid) ----
__global__ void __launch_bounds__(128) k_spmm(const float* __restrict__ b, int n0) {
    int w    = threadIdx.x >> 5;
    int lane = threadIdx.x & 31;
    int c    = n0 + blockIdx.x * 4 + w;
    unsigned base = (unsigned)c * BUCKET;
    int cnt = min(g_cnt[c], BUCKET);
    __syncwarp();
    if (lane == 0) g_cnt[c] = 0;            // replay cleanup (warp-private node)

    unsigned col = lane * 4;
    float4 a0 = {0,0,0,0}, a1 = {0,0,0,0}, a2 = {0,0,0,0}, a3 = {0,0,0,0};
    int i = 0;
#pragma unroll 2
    for (; i + 3 < cnt; i += 4) {
        int4 s4 = *(const int4*)&g_src[base + i];      // uniform LDG.128
        float w0 = g_dinv[s4.x], w1 = g_dinv[s4.y];
        float w2 = g_dinv[s4.z], w3 = g_dinv[s4.w];
        float4 v0 = *(const float4*)&g_xw[(unsigned)s4.x * NHID + col];
        float4 v1 = *(const float4*)&g_xw[(unsigned)s4.y * NHID + col];
        float4 v2 = *(const float4*)&g_xw[(unsigned)s4.z * NHID + col];
        float4 v3 = *(const float4*)&g_xw[(unsigned)s4.w * NHID + col];
        a0.x = fmaf(w0, v0.x, a0.x); a0.y = fmaf(w0, v0.y, a0.y);
        a0.z = fmaf(w0, v0.z, a0.z); a0.w = fmaf(w0, v0.w, a0.w);
        a1.x = fmaf(w1, v1.x, a1.x); a1.y = fmaf(w1, v1.y, a1.y);
        a1.z = fmaf(w1, v1.z, a1.z); a1.w = fmaf(w1, v1.w, a1.w);
        a2.x = fmaf(w2, v2.x, a2.x); a2.y = fmaf(w2, v2.y, a2.y);
        a2.z = fmaf(w2, v2.z, a2.z); a2.w = fmaf(w2, v2.w, a2.w);
        a3.x = fmaf(w3, v3.x, a3.x); a3.y = fmaf(w3, v3.y, a3.y);
        a3.z = fmaf(w3, v3.z, a3.z); a3.w = fmaf(w3, v3.w, a3.w);
    }
    for (; i < cnt; i++) {
        int s = g_src[base + i];
        float ws = g_dinv[s];
        float4 v = *(const float4*)&g_xw[(unsigned)s * NHID + col];
        a0.x = fmaf(ws, v.x, a0.x); a0.y = fmaf(ws, v.y, a0.y);
        a0.z = fmaf(ws, v.z, a0.z); a0.w = fmaf(ws, v.w, a0.w);
    }

    float dc  = g_dinv[c];
    float dc2 = dc * dc;
    float4 xv = *(const float4*)&g_xw[(unsigned)c * NHID + col];
    float4 bv = *(const float4*)&b[col];
    float4 s;
    s.x = fmaxf(dc * ((a0.x + a1.x) + (a2.x + a3.x)) + dc2 * xv.x + bv.x, 0.0f);
    s.y = fmaxf(dc * ((a0.y + a1.y) + (a2.y + a3.y)) + dc2 * xv.y + bv.y, 0.0f);
    s.z = fmaxf(dc * ((a0.z + a1.z) + (a2.z + a3.z)) + dc2 * xv.z + bv.z, 0.0f);
    s.w = fmaxf(dc * ((a0.w + a1.w) + (a2.w + a3.w)) + dc2 * xv.w + bv.w, 0.0f);

    __nv_bfloat162 p0 = __floats2bfloat162_rn(s.x, s.y);
    __nv_bfloat162 p1 = __floats2bfloat162_rn(s.z, s.w);
    uint2 packed = make_uint2(*(unsigned*)&p0, *(unsigned*)&p1);
    *(uint2*)&g_hb[(unsigned)c * NHID + col] = packed;
}

// ---- out = h @ h^T : bf16 mma.sync + ldmatrix; phase-masked tiles ----
// phase 0: bi,bj < TSPLIT only.  phase 1: all other upper-tri tiles.
__global__ void __launch_bounds__(256) k_gemm(float* __restrict__ out, int phase) {
    extern __shared__ char smem[];
    int bi = blockIdx.y, bj = blockIdx.x;
    if (bj < bi) return;
    bool lo = (bi < TSPLIT) && (bj < TSPLIT);
    if (phase == 0 ? !lo : lo) return;
    bool diag = (bi == bj);

    unsigned sA = smem_u32(smem);
    unsigned sB = sA + 32768u;

    int t = threadIdx.x, lane = t & 31, wid = t >> 5;
    const __nv_bfloat16* gA = g_hb + (size_t)bi * 128 * NHID;
    const __nv_bfloat16* gB = g_hb + (size_t)bj * 128 * NHID;

#pragma unroll
    for (int p = 0; p < 8; p++) {
        int chunk = p * 256 + t;
        int row = chunk >> 4, kc = chunk & 15;
        unsigned off = (unsigned)row * 256u + (unsigned)((kc ^ (row & 7)) << 4);
        *(uint4*)(smem + off) = *(const uint4*)(gA + row * NHID + kc * 8);
        if (!diag)
            *(uint4*)(smem + 32768 + off) = *(const uint4*)(gB + row * NHID + kc * 8);
    }
    __syncthreads();

    unsigned bB = diag ? sA : sB;
    int wm = wid & 3;
    int wn = wid >> 2;
    int mat = lane >> 3, rin = lane & 7;
    int rowoff = rin + (mat & 1) * 8;
    int khalf  = mat >> 1;

    float acc[2][8][4] = {};

#pragma unroll
    for (int ks = 0; ks < 8; ks++) {
        int kc = ks * 2 + khalf;
        unsigned a[2][4];
#pragma unroll
        for (int mi = 0; mi < 2; mi++) {
            int row = wm * 32 + mi * 16 + rowoff;
            unsigned addr = sA + (unsigned)row * 256u + (unsigned)((kc ^ (row & 7)) << 4);
            asm volatile("ldmatrix.sync.aligned.m8n8.x4.shared.b16 {%0,%1,%2,%3}, [%4];"
                : "=r"(a[mi][0]), "=r"(a[mi][1]), "=r"(a[mi][2]), "=r"(a[mi][3])
                : "r"(addr));
        }
        unsigned bf[4][4];
#pragma unroll
        for (int nb = 0; nb < 4; nb++) {
            int row = wn * 64 + nb * 16 + rowoff;
            unsigned addr = bB + (unsigned)row * 256u + (unsigned)((kc ^ (row & 7)) << 4);
            asm volatile("ldmatrix.sync.aligned.m8n8.x4.shared.b16 {%0,%1,%2,%3}, [%4];"
                : "=r"(bf[nb][0]), "=r"(bf[nb][1]), "=r"(bf[nb][2]), "=r"(bf[nb][3])
                : "r"(addr));
        }
#pragma unroll
        for (int mi = 0; mi < 2; mi++)
#pragma unroll
            for (int nb = 0; nb < 4; nb++) {
                float* d0 = acc[mi][nb * 2 + 0];
                float* d1 = acc[mi][nb * 2 + 1];
                asm volatile(
                    "mma.sync.aligned.m16n8k16.row.col.f32.bf16.bf16.f32 "
                    "{%0,%1,%2,%3}, {%4,%5,%6,%7}, {%8,%9}, {%0,%1,%2,%3};"
                    : "+f"(d0[0]), "+f"(d0[1]), "+f"(d0[2]), "+f"(d0[3])
                    : "r"(a[mi][0]), "r"(a[mi][1]), "r"(a[mi][2]), "r"(a[mi][3]),
                      "r"(bf[nb][0]), "r"(bf[nb][2]));
                asm volatile(
                    "mma.sync.aligned.m16n8k16.row.col.f32.bf16.bf16.f32 "
                    "{%0,%1,%2,%3}, {%4,%5,%6,%7}, {%8,%9}, {%0,%1,%2,%3};"
                    : "+f"(d1[0]), "+f"(d1[1]), "+f"(d1[2]), "+f"(d1[3])
                    : "r"(a[mi][0]), "r"(a[mi][1]), "r"(a[mi][2]), "r"(a[mi][3]),
                      "r"(bf[nb][1]), "r"(bf[nb][3]));
            }
    }

    int g = lane >> 2, tq = lane & 3;
    int r0 = bi * 128, c0 = bj * 128;
    bool interior = (bi < NT - 1) && (bj < NT - 1);

    if (interior) {
#pragma unroll
        for (int mi = 0; mi < 2; mi++)
#pragma unroll
            for (int ni = 0; ni < 8; ni++) {
                float* d = acc[mi][ni];
                int r = r0 + wm * 32 + mi * 16 + g;
                int c = c0 + wn * 64 + ni * 8 + 2 * tq;
                *(float2*)&out[(size_t)r * N_NODES + c]       = make_float2(d[0], d[1]);
                *(float2*)&out[(size_t)(r + 8) * N_NODES + c] = make_float2(d[2], d[3]);
                if (!diag) {
                    out[(size_t)c * N_NODES + r]           = d[0];
                    out[(size_t)(c + 1) * N_NODES + r]     = d[1];
                    out[(size_t)c * N_NODES + r + 8]       = d[2];
                    out[(size_t)(c + 1) * N_NODES + r + 8] = d[3];
                }
            }
    } else {
#pragma unroll
        for (int mi = 0; mi < 2; mi++)
#pragma unroll
            for (int ni = 0; ni < 8; ni++) {
                float* d = acc[mi][ni];
                int r = r0 + wm * 32 + mi * 16 + g;
                int c = c0 + wn * 64 + ni * 8 + 2 * tq;
#pragma unroll
                for (int q = 0; q < 4; q++) {
                    int rr = r + (q >> 1) * 8, cc = c + (q & 1);
                    if (rr < N_NODES && cc < N_NODES) {
                        out[(size_t)rr * N_NODES + cc] = d[q];
                        if (!diag) out[(size_t)cc * N_NODES + rr] = d[q];
                    }
                }
            }
    }
}

extern "C" void kernel_launch(void* const* d_in, const int* in_sizes, int n_in,
                              void* d_out, int out_size) {
    const float* x  = nullptr;
    const int*   ei = nullptr;
    const float* W  = nullptr;
    const float* b  = nullptr;
    for (int i = 0; i < n_in; i++) {
        switch (in_sizes[i]) {
            case N_NODES * NHID: x  = (const float*)d_in[i]; break;
            case 2 * NEDGE:      ei = (const int*)d_in[i];   break;
            case NHID * NHID:    W  = (const float*)d_in[i]; break;
            case NHID:           b  = (const float*)d_in[i]; break;
            default: break;
        }
    }
    float* out = (float*)d_out;

    static cudaStream_t s2 = nullptr;
    static cudaEvent_t  evFork = nullptr, evXw = nullptr, evLo = nullptr, evG = nullptr;
    static int initialized = 0;
    if (!initialized) {
        cudaFuncSetAttribute(k_gemm, cudaFuncAttributeMaxDynamicSharedMemorySize,
                             GEMM_SMEM);
        cudaFuncSetAttribute(k_xw, cudaFuncAttributeMaxDynamicSharedMemorySize,
                             XW_SMEM);
        cudaStreamCreateWithFlags(&s2, cudaStreamNonBlocking);
        cudaEventCreateWithFlags(&evFork, cudaEventDisableTiming);
        cudaEventCreateWithFlags(&evXw, cudaEventDisableTiming);
        cudaEventCreateWithFlags(&evLo, cudaEventDisableTiming);
        cudaEventCreateWithFlags(&evG, cudaEventDisableTiming);
        initialized = 1;
    }

    dim3 ggLo(TSPLIT, TSPLIT);
    dim3 gg(NT, NT);

    // fork: k_xw runs concurrent with the bucket-CSR build
    cudaEventRecord(evFork, 0);
    cudaStreamWaitEvent(s2, evFork, 0);
    k_xw<<<(N_NODES + 63) / 64, 512, XW_SMEM, s2>>>(x, W);
    cudaEventRecord(evXw, s2);

    k_fill2<<<(NEDGE + 255) / 256, 256>>>(ei);
    k_dinv <<<(N_NODES + 255) / 256, 256>>>();

    // join xw, then spmm for the lo node range
    cudaStreamWaitEvent(0, evXw, 0);
    k_spmm<<<NSPLIT / 4, 128>>>(b, 0);
    cudaEventRecord(evLo, 0);

    // side stream: gemm over lo-only tiles, concurrent with spmm_hi
    cudaStreamWaitEvent(s2, evLo, 0);
    k_gemm<<<ggLo, 256, GEMM_SMEM, s2>>>(out, 0);
    cudaEventRecord(evG, s2);

    // main: spmm for hi nodes, then the remaining gemm tiles
    k_spmm<<<(N_NODES - NSPLIT) / 4, 128>>>(b, NSPLIT);
    k_gemm<<<gg, 256, GEMM_SMEM>>>(out, 1);

    // join side stream before returning
    cudaStreamWaitEvent(0, evG, 0);
}